// round 10
// baseline (speedup 1.0000x reference)
#include <cuda_runtime.h>
#include <cuda_bf16.h>
#include <cuda_fp16.h>
#include <cstdint>
#include <math.h>

// ---------------- problem constants ----------------
static constexpr int N_NODES = 50000;
static constexpr int N_EDGES = 400000;
static constexpr int D_IN    = 256;
static constexpr int C1      = 128;   // HEADS*H1
static constexpr int C2      = 64;    // H2
static constexpr int BATCH   = 4096;
static constexpr int DEC     = 512;

// output layout (tuple flattened in order)
static constexpr int OFF_LOG    = 0;
static constexpr int OFF_RET    = OFF_LOG + BATCH * 2;          // 8192
static constexpr int OFF_RETA   = OFF_RET + N_NODES * 2;        // 108192
static constexpr int OFF_X2     = OFF_RETA + N_NODES * 2;       // 208192
static constexpr int OFF_LOGITS = OFF_X2 + N_NODES * C2;        // 3408192
static constexpr int OFF_LOG1   = OFF_LOGITS + 2 * N_NODES;     // 3508192

// weight-split offsets (elements)
static constexpr int WOFF_W1  = 0;                  // 256*128 = 32768
static constexpr int WOFF_W2  = 32768;              // 128*64  = 8192
static constexpr int WOFF_FW1 = 40960;              // 128*512 = 65536
static constexpr int WSPLIT_TOTAL = 106496;

// ---------------- device scratch ----------------
__device__ __half  g_h1[2 * N_NODES * C1];
__device__ __half  g_x1[2 * N_NODES * C1];
__device__ __half  g_h2[2 * N_NODES * C2];
__device__ float   g_x2[2 * N_NODES * C2];
__device__ float   g_as1[2 * N_NODES * 4];
__device__ float   g_ad1[2 * N_NODES * 4];
__device__ float   g_as2[2 * N_NODES];
__device__ float   g_ad2[2 * N_NODES];
__device__ int     g_cnt[N_NODES];
__device__ int     g_off[N_NODES + 1];
__device__ int     g_cur[N_NODES];
__device__ int     g_csr[N_EDGES];
__device__ int     g_bsum[64];
__device__ int     g_bpre[64];
__device__ float   g_sums[128];
__device__ float   g_small[200];
__device__ float   g_fh[BATCH * DEC];
__device__ __nv_bfloat16 g_whi[WSPLIT_TOTAL];
__device__ __nv_bfloat16 g_wlo[WSPLIT_TOTAL];

// ---------------- helpers ----------------
__device__ __forceinline__ float leaky02(float x) { return x >= 0.f ? x : 0.2f * x; }
__device__ __forceinline__ float prelu_f(float x, float w) { return x >= 0.f ? x : w * x; }
__device__ __forceinline__ float warp_sum(float v) {
#pragma unroll
    for (int o = 16; o > 0; o >>= 1) v += __shfl_xor_sync(0xffffffffu, v, o);
    return v;
}
__device__ __forceinline__ float quad_sum(float v) {
    v += __shfl_xor_sync(0xffffffffu, v, 1);
    v += __shfl_xor_sync(0xffffffffu, v, 2);
    return v;
}
__device__ __forceinline__ unsigned smem_u32(const void* p) {
    return (unsigned)__cvta_generic_to_shared(p);
}
__device__ __forceinline__ float4 ldh4(const __half* p) {
    uint2 u = *reinterpret_cast<const uint2*>(p);
    float2 a = __half22float2(*reinterpret_cast<__half2*>(&u.x));
    float2 b = __half22float2(*reinterpret_cast<__half2*>(&u.y));
    return make_float4(a.x, a.y, b.x, b.y);
}
__device__ __forceinline__ float2 ldh2(const __half* p) {
    __half2 h = *reinterpret_cast<const __half2*>(p);
    return __half22float2(h);
}
__device__ __forceinline__ void sth4(__half* p, float4 v) {
    uint2 u;
    __half2 a = __floats2half2_rn(v.x, v.y);
    __half2 b = __floats2half2_rn(v.z, v.w);
    u.x = *reinterpret_cast<unsigned*>(&a);
    u.y = *reinterpret_cast<unsigned*>(&b);
    *reinterpret_cast<uint2*>(p) = u;
}

// ---------------- tensor-core primitives ----------------
__device__ __forceinline__ void ldm_x4(unsigned r[4], unsigned addr) {
    asm volatile("ldmatrix.sync.aligned.m8n8.x4.shared.b16 {%0,%1,%2,%3}, [%4];"
                 : "=r"(r[0]), "=r"(r[1]), "=r"(r[2]), "=r"(r[3]) : "r"(addr));
}
__device__ __forceinline__ void ldm_x2t(unsigned r[2], unsigned addr) {
    asm volatile("ldmatrix.sync.aligned.m8n8.x2.trans.shared.b16 {%0,%1}, [%2];"
                 : "=r"(r[0]), "=r"(r[1]) : "r"(addr));
}
__device__ __forceinline__ void mma_bf16(float d[4], const unsigned a[4], const unsigned b[2]) {
    asm volatile("mma.sync.aligned.m16n8k16.row.col.f32.bf16.bf16.f32 "
                 "{%0,%1,%2,%3},{%4,%5,%6,%7},{%8,%9},{%0,%1,%2,%3};"
                 : "+f"(d[0]), "+f"(d[1]), "+f"(d[2]), "+f"(d[3])
                 : "r"(a[0]), "r"(a[1]), "r"(a[2]), "r"(a[3]), "r"(b[0]), "r"(b[1]));
}

// split fp32 -> bf16 hi + bf16 lo, store 4 values (8B) to each smem buffer
__device__ __forceinline__ void store_split(__nv_bfloat16* hi, __nv_bfloat16* lo, float4 v) {
    __nv_bfloat16 h0 = __float2bfloat16(v.x), h1 = __float2bfloat16(v.y),
                  h2 = __float2bfloat16(v.z), h3 = __float2bfloat16(v.w);
    __nv_bfloat16 l0 = __float2bfloat16(v.x - __bfloat162float(h0)),
                  l1 = __float2bfloat16(v.y - __bfloat162float(h1)),
                  l2 = __float2bfloat16(v.z - __bfloat162float(h2)),
                  l3 = __float2bfloat16(v.w - __bfloat162float(h3));
    __nv_bfloat162 hp0 = __halves2bfloat162(h0, h1), hp1 = __halves2bfloat162(h2, h3);
    __nv_bfloat162 lp0 = __halves2bfloat162(l0, l1), lp1 = __halves2bfloat162(l2, l3);
    *reinterpret_cast<uint2*>(hi) =
        make_uint2(*reinterpret_cast<unsigned*>(&hp0), *reinterpret_cast<unsigned*>(&hp1));
    *reinterpret_cast<uint2*>(lo) =
        make_uint2(*reinterpret_cast<unsigned*>(&lp0), *reinterpret_cast<unsigned*>(&lp1));
}

// ---------------- weight pre-split (once per launch) ----------------
__global__ void k_splitW(const float* __restrict__ W1, const float* __restrict__ W2,
                         const float* __restrict__ fW1, __nv_bfloat16* __restrict__ hi,
                         __nv_bfloat16* __restrict__ lo) {
    int i = blockIdx.x * 256 + threadIdx.x;
    if (i >= WSPLIT_TOTAL) return;
    float v;
    if (i < WOFF_W2) v = W1[i];
    else if (i < WOFF_FW1) v = W2[i - WOFF_W2];
    else v = fW1[i - WOFF_FW1];
    __nv_bfloat16 h = __float2bfloat16(v);
    hi[i] = h;
    lo[i] = __float2bfloat16(v - __bfloat162float(h));
}

// ---------------- split-bf16 tensor-core GEMM: C = A @ B (pre-split bf16 B) ----------------
template <int BN, int WM, int WN, int MODE, int EPI, int OUTC, int INA>
__global__ void __launch_bounds__(256)
k_mma_gemm(const void* __restrict__ A0v, const void* __restrict__ A1v,
           const __nv_bfloat16* __restrict__ BhiG, const __nv_bfloat16* __restrict__ BloG,
           const float* __restrict__ bias, void* __restrict__ Cout,
           int M, int N, int K, int Msplit,
           const int* __restrict__ idx0, const int* __restrict__ idx1,
           const float* __restrict__ asrc, const float* __restrict__ adst,
           float* __restrict__ as_out, float* __restrict__ ad_out) {
    constexpr int BM = 128, BK = 32;
    constexpr int APAD = BK + 8;
    constexpr int BPAD = BN + 8;
    constexpr int WTM = BM / WM, WTN = BN / WN;
    constexpr int MT = WTM / 16, NT = WTN / 8;
    constexpr int A_ITERS = BM * BK / 1024;
    constexpr int B_IT = (BK * BN) / 2048;
    constexpr int ASZ = BM * APAD;
    constexpr int BSZ = BK * BPAD;

    extern __shared__ __align__(16) char dynsmem[];
    __nv_bfloat16* Ahi = reinterpret_cast<__nv_bfloat16*>(dynsmem);
    __nv_bfloat16* Alo = Ahi + 2 * ASZ;
    __nv_bfloat16* Bhi = Alo + 2 * ASZ;
    __nv_bfloat16* Blo = Bhi + 2 * BSZ;

    const int tid = threadIdx.x, lane = tid & 31, warp = tid >> 5;
    const int wy = warp / WN, wx = warp % WN;
    const int row0 = blockIdx.y * BM, col0 = blockIdx.x * BN;

    float acc[MT][NT][4];
#pragma unroll
    for (int i = 0; i < MT; i++)
#pragma unroll
        for (int j = 0; j < NT; j++)
#pragma unroll
            for (int q = 0; q < 4; q++) acc[i][j][q] = 0.f;

    float4 aReg[A_ITERS];
    uint4 bRegH[B_IT], bRegL[B_IT];

    auto loadTiles = [&](int k0) {
#pragma unroll
        for (int it = 0; it < A_ITERS; it++) {
            int idx = tid + it * 256;
            int r = idx >> 3, c = (idx & 7) << 2;
            int gr = row0 + r;
            float4 v = make_float4(0.f, 0.f, 0.f, 0.f);
            if (MODE == 2) {
                int node = (k0 < C2) ? idx0[gr] : idx1[gr];
                int kc = (k0 & (C2 - 1)) + c;
                v = *reinterpret_cast<const float4*>((const float*)A0v + (size_t)node * C2 + kc);
            } else if (gr < M) {
                if (INA == 1) {
                    v = ldh4((const __half*)A0v + (size_t)gr * K + k0 + c);
                } else {
                    const float* Ap;
                    if (MODE == 1)
                        Ap = (gr < Msplit) ? (const float*)A0v + (size_t)gr * K
                                           : (const float*)A1v + (size_t)(gr - Msplit) * K;
                    else
                        Ap = (const float*)A0v + (size_t)gr * K;
                    v = *reinterpret_cast<const float4*>(Ap + k0 + c);
                }
            }
            aReg[it] = v;
        }
#pragma unroll
        for (int it = 0; it < B_IT; it++) {
            int idx = tid + it * 256;
            int r = idx / (BN / 8), c = (idx % (BN / 8)) * 8;
            size_t g = (size_t)(k0 + r) * N + col0 + c;
            bRegH[it] = *reinterpret_cast<const uint4*>(BhiG + g);
            bRegL[it] = *reinterpret_cast<const uint4*>(BloG + g);
        }
    };

    auto storeTiles = [&](int buf) {
#pragma unroll
        for (int it = 0; it < A_ITERS; it++) {
            int idx = tid + it * 256;
            int r = idx >> 3, c = (idx & 7) << 2;
            store_split(&Ahi[buf * ASZ + r * APAD + c], &Alo[buf * ASZ + r * APAD + c], aReg[it]);
        }
#pragma unroll
        for (int it = 0; it < B_IT; it++) {
            int idx = tid + it * 256;
            int r = idx / (BN / 8), c = (idx % (BN / 8)) * 8;
            *reinterpret_cast<uint4*>(&Bhi[buf * BSZ + r * BPAD + c]) = bRegH[it];
            *reinterpret_cast<uint4*>(&Blo[buf * BSZ + r * BPAD + c]) = bRegL[it];
        }
    };

    const int nT = K / BK;
    loadTiles(0);
    storeTiles(0);
    __syncthreads();

    for (int t = 0; t < nT; t++) {
        int cur = t & 1;
        if (t + 1 < nT) loadTiles((t + 1) * BK);
#pragma unroll
        for (int ks = 0; ks < 2; ks++) {
            unsigned ah[MT][4], al[MT][4];
#pragma unroll
            for (int i = 0; i < MT; i++) {
                int arow = wy * WTM + i * 16 + (lane & 15);
                int acol = ks * 16 + ((lane >> 4) << 3);
                ldm_x4(ah[i], smem_u32(&Ahi[cur * ASZ + arow * APAD + acol]));
                ldm_x4(al[i], smem_u32(&Alo[cur * ASZ + arow * APAD + acol]));
            }
#pragma unroll
            for (int j = 0; j < NT; j++) {
                int brow = ks * 16 + (lane & 15);
                int bcol = wx * WTN + j * 8;
                unsigned bh[2], bl[2];
                ldm_x2t(bh, smem_u32(&Bhi[cur * BSZ + brow * BPAD + bcol]));
                ldm_x2t(bl, smem_u32(&Blo[cur * BSZ + brow * BPAD + bcol]));
#pragma unroll
                for (int i = 0; i < MT; i++) {
                    mma_bf16(acc[i][j], ah[i], bh);
                    mma_bf16(acc[i][j], ah[i], bl);
                    mma_bf16(acc[i][j], al[i], bh);
                }
            }
        }
        if (t + 1 < nT) storeTiles(cur ^ 1);
        __syncthreads();
    }

    // --- C store ---
#pragma unroll
    for (int i = 0; i < MT; i++) {
        int rg = row0 + wy * WTM + i * 16 + (lane >> 2);
#pragma unroll
        for (int j = 0; j < NT; j++) {
            int cg = col0 + wx * WTN + j * 8 + (lane & 3) * 2;
            float2 v0 = make_float2(acc[i][j][0], acc[i][j][1]);
            float2 v1 = make_float2(acc[i][j][2], acc[i][j][3]);
            if (MODE == 2) {
                float b0 = bias[cg], b1 = bias[cg + 1];
                v0.x = fmaxf(v0.x + b0, 0.f); v0.y = fmaxf(v0.y + b1, 0.f);
                v1.x = fmaxf(v1.x + b0, 0.f); v1.y = fmaxf(v1.y + b1, 0.f);
            }
            if (OUTC == 1) {
                __half* C = (__half*)Cout;
                if (rg < M)
                    *reinterpret_cast<__half2*>(C + (size_t)rg * N + cg) = __floats2half2_rn(v0.x, v0.y);
                if (rg + 8 < M)
                    *reinterpret_cast<__half2*>(C + (size_t)(rg + 8) * N + cg) = __floats2half2_rn(v1.x, v1.y);
            } else {
                float* C = (float*)Cout;
                if (rg < M)
                    *reinterpret_cast<float2*>(C + (size_t)rg * N + cg) = v0;
                if (rg + 8 < M)
                    *reinterpret_cast<float2*>(C + (size_t)(rg + 8) * N + cg) = v1;
            }
        }
    }

    // --- fused attention-logit epilogue ---
    if (EPI != 0) {
        const int head = (EPI == 1) ? wx : 0;
        const int hstride = (EPI == 1) ? 4 : 1;
        float2 ws[NT], wd[NT];
#pragma unroll
        for (int j = 0; j < NT; j++) {
            int f = head * 32 + j * 8 + (lane & 3) * 2;
            ws[j] = *reinterpret_cast<const float2*>(asrc + f);
            wd[j] = *reinterpret_cast<const float2*>(adst + f);
        }
#pragma unroll
        for (int i = 0; i < MT; i++) {
            float ds0 = 0.f, dd0 = 0.f, ds1 = 0.f, dd1 = 0.f;
#pragma unroll
            for (int j = 0; j < NT; j++) {
                ds0 += acc[i][j][0] * ws[j].x + acc[i][j][1] * ws[j].y;
                ds1 += acc[i][j][2] * ws[j].x + acc[i][j][3] * ws[j].y;
                dd0 += acc[i][j][0] * wd[j].x + acc[i][j][1] * wd[j].y;
                dd1 += acc[i][j][2] * wd[j].x + acc[i][j][3] * wd[j].y;
            }
            ds0 = quad_sum(ds0); ds1 = quad_sum(ds1);
            dd0 = quad_sum(dd0); dd1 = quad_sum(dd1);
            if ((lane & 3) == 0) {
                int r0 = row0 + wy * WTM + i * 16 + (lane >> 2);
                if (r0 < M) {
                    as_out[(size_t)r0 * hstride + head] = ds0;
                    ad_out[(size_t)r0 * hstride + head] = dd0;
                }
                if (r0 + 8 < M) {
                    as_out[(size_t)(r0 + 8) * hstride + head] = ds1;
                    ad_out[(size_t)(r0 + 8) * hstride + head] = dd1;
                }
            }
        }
    }
}

// ---------------- CSR build ----------------
__global__ void k_zero(int* cnt, float* sums) {
    int i = blockIdx.x * blockDim.x + threadIdx.x;
    if (i < N_NODES) cnt[i] = 0;
    if (i < 128) sums[i] = 0.f;
}

__global__ void k_hist(const int* __restrict__ dst, int* __restrict__ cnt) {
    int e = blockIdx.x * blockDim.x + threadIdx.x;
    if (e < N_EDGES) atomicAdd(&cnt[dst[e]], 1);
}

// two-level scan: A) per-block local exclusive scan, B) scan block sums, C) add offsets
__global__ void k_scanA(const int* __restrict__ cnt, int* __restrict__ off,
                        int* __restrict__ bsum) {
    __shared__ int ws[32];
    int i = blockIdx.x * 1024 + threadIdx.x;
    int lane = threadIdx.x & 31, wid = threadIdx.x >> 5;
    int v = (i < N_NODES) ? cnt[i] : 0;
    int x = v;
#pragma unroll
    for (int o = 1; o < 32; o <<= 1) {
        int t = __shfl_up_sync(0xffffffffu, x, o);
        if (lane >= o) x += t;
    }
    if (lane == 31) ws[wid] = x;
    __syncthreads();
    if (wid == 0) {
        int w = ws[lane];
#pragma unroll
        for (int o = 1; o < 32; o <<= 1) {
            int t = __shfl_up_sync(0xffffffffu, w, o);
            if (lane >= o) w += t;
        }
        ws[lane] = w;
    }
    __syncthreads();
    int incl = x + (wid > 0 ? ws[wid - 1] : 0);
    if (i < N_NODES) off[i] = incl - v;
    if (threadIdx.x == 1023) bsum[blockIdx.x] = incl;
}

__global__ void k_scanB(const int* __restrict__ bsum, int* __restrict__ bpre,
                        int* __restrict__ off, int nblocks) {
    __shared__ int s[64];
    int tid = threadIdx.x;
    int v = (tid < nblocks) ? bsum[tid] : 0;
    s[tid] = v;
    __syncthreads();
    for (int o = 1; o < 64; o <<= 1) {
        int t = (tid >= o) ? s[tid - o] : 0;
        __syncthreads();
        s[tid] += t;
        __syncthreads();
    }
    bpre[tid] = s[tid] - v;
    if (tid == 63) off[N_NODES] = s[63];
}

__global__ void k_scanC(int* __restrict__ off, int* __restrict__ cur,
                        const int* __restrict__ bpre) {
    int i = blockIdx.x * 1024 + threadIdx.x;
    if (i < N_NODES) {
        int t = off[i] + bpre[blockIdx.x];
        off[i] = t;
        cur[i] = t;
    }
}

__global__ void k_fill(const int* __restrict__ src, const int* __restrict__ dst,
                       int* __restrict__ cur, int* __restrict__ csr) {
    int e = blockIdx.x * blockDim.x + threadIdx.x;
    if (e < N_EDGES) {
        int d = dst[e];
        int p = atomicAdd(&cur[d], 1);
        csr[p] = src[e];
    }
}

// ---------------- GAT aggregation layer 1 (online softmax, 4-edge pipelined) --------------
__global__ void k_agg1(const __half* __restrict__ h1, const float* __restrict__ as_,
                       const float* __restrict__ ad_, const float* __restrict__ b1,
                       const float* __restrict__ p1, __half* __restrict__ x1,
                       const int* __restrict__ off, const int* __restrict__ csr) {
    int n = (blockIdx.x * blockDim.x + threadIdx.x) >> 5;
    int lane = threadIdx.x & 31;
    if (n >= N_NODES) return;
    int na = n + N_NODES;
    int h = lane >> 3;
    float adh_o = ad_[(size_t)n * 4 + h];
    float adh_a = ad_[(size_t)na * 4 + h];
    int beg = off[n], end = off[n + 1];

    float m_o = leaky02(as_[(size_t)n * 4 + h] + adh_o);
    float m_a = leaky02(as_[(size_t)na * 4 + h] + adh_a);
    float den_o = 1.f, den_a = 1.f;
    float4 v_o = ldh4(h1 + (size_t)n * C1 + lane * 4);
    float4 v_a = ldh4(h1 + (size_t)na * C1 + lane * 4);
    float ox = v_o.x, oy = v_o.y, oz = v_o.z, ow = v_o.w;
    float ax = v_a.x, ay = v_a.y, az = v_a.z, aw = v_a.w;

    for (int j = beg; j < end; j += 4) {
        // batch-load 4 edge indices (independent)
        int sb[4];
#pragma unroll
        for (int t = 0; t < 4; t++)
            sb[t] = (j + t < end) ? csr[j + t] : n;   // pad with self (valid addr, weight 0)
        bool valid[4];
#pragma unroll
        for (int t = 0; t < 4; t++) valid[t] = (j + t < end);
        // batch-load logits + gather rows (all independent of accumulation)
        float eo[4], ea[4];
        float4 ho[4], ha[4];
#pragma unroll
        for (int t = 0; t < 4; t++) {
            int s = sb[t];
            eo[t] = valid[t] ? leaky02(as_[(size_t)s * 4 + h] + adh_o) : -1e30f;
            ea[t] = valid[t] ? leaky02(as_[(size_t)(s + N_NODES) * 4 + h] + adh_a) : -1e30f;
            ho[t] = ldh4(h1 + (size_t)s * C1 + lane * 4);
            ha[t] = ldh4(h1 + (size_t)(s + N_NODES) * C1 + lane * 4);
        }
        // serial online-softmax accumulation (ALU only)
#pragma unroll
        for (int t = 0; t < 4; t++) {
            float mn_o = fmaxf(m_o, eo[t]), mn_a = fmaxf(m_a, ea[t]);
            float sc_o = __expf(m_o - mn_o), sc_a = __expf(m_a - mn_a);
            float w_o = __expf(eo[t] - mn_o), w_a = __expf(ea[t] - mn_a);
            ox = ox * sc_o + ho[t].x * w_o; oy = oy * sc_o + ho[t].y * w_o;
            oz = oz * sc_o + ho[t].z * w_o; ow = ow * sc_o + ho[t].w * w_o;
            ax = ax * sc_a + ha[t].x * w_a; ay = ay * sc_a + ha[t].y * w_a;
            az = az * sc_a + ha[t].z * w_a; aw = aw * sc_a + ha[t].w * w_a;
            den_o = den_o * sc_o + w_o;
            den_a = den_a * sc_a + w_a;
            m_o = mn_o; m_a = mn_a;
        }
    }
    float inv_o = 1.f / (den_o + 1e-16f);
    float inv_a = 1.f / (den_a + 1e-16f);
    int c = lane * 4;
    float4 bb = *reinterpret_cast<const float4*>(b1 + c);
    float4 pp = *reinterpret_cast<const float4*>(p1 + c);
    float4 out_o, out_a;
    out_o.x = prelu_f(ox * inv_o + bb.x, pp.x);
    out_o.y = prelu_f(oy * inv_o + bb.y, pp.y);
    out_o.z = prelu_f(oz * inv_o + bb.z, pp.z);
    out_o.w = prelu_f(ow * inv_o + bb.w, pp.w);
    out_a.x = prelu_f(ax * inv_a + bb.x, pp.x);
    out_a.y = prelu_f(ay * inv_a + bb.y, pp.y);
    out_a.z = prelu_f(az * inv_a + bb.z, pp.z);
    out_a.w = prelu_f(aw * inv_a + bb.w, pp.w);
    sth4(x1 + (size_t)n * C1 + c, out_o);
    sth4(x1 + (size_t)na * C1 + c, out_a);
}

// ---------------- GAT aggregation layer 2 (online softmax, 4-edge pipelined, colsum) ------
__global__ void k_agg2(const __half* __restrict__ h2, const float* __restrict__ as_,
                       const float* __restrict__ ad_, const float* __restrict__ b2,
                       const float* __restrict__ p2, float* __restrict__ x2,
                       const int* __restrict__ off, const int* __restrict__ csr,
                       float* __restrict__ sums) {
    __shared__ float s_o[64], s_a[64];
    int tid = threadIdx.x;
    int n = (blockIdx.x * blockDim.x + tid) >> 5;
    int lane = tid & 31;
    if (tid < 64) { s_o[tid] = 0.f; s_a[tid] = 0.f; }
    __syncthreads();

    int na = n + N_NODES;
    float adh_o = ad_[n], adh_a = ad_[na];
    int beg = off[n], end = off[n + 1];

    float m_o = leaky02(as_[n] + adh_o);
    float m_a = leaky02(as_[na] + adh_a);
    float den_o = 1.f, den_a = 1.f;
    float2 v_o = ldh2(h2 + (size_t)n * C2 + lane * 2);
    float2 v_a = ldh2(h2 + (size_t)na * C2 + lane * 2);
    float ox = v_o.x, oy = v_o.y, ax = v_a.x, ay = v_a.y;

    for (int j = beg; j < end; j += 4) {
        int sb[4];
#pragma unroll
        for (int t = 0; t < 4; t++)
            sb[t] = (j + t < end) ? csr[j + t] : n;
        bool valid[4];
#pragma unroll
        for (int t = 0; t < 4; t++) valid[t] = (j + t < end);
        float eo[4], ea[4];
        float2 ho[4], ha[4];
#pragma unroll
        for (int t = 0; t < 4; t++) {
            int s = sb[t];
            eo[t] = valid[t] ? leaky02(as_[s] + adh_o) : -1e30f;
            ea[t] = valid[t] ? leaky02(as_[s + N_NODES] + adh_a) : -1e30f;
            ho[t] = ldh2(h2 + (size_t)s * C2 + lane * 2);
            ha[t] = ldh2(h2 + (size_t)(s + N_NODES) * C2 + lane * 2);
        }
#pragma unroll
        for (int t = 0; t < 4; t++) {
            float mn_o = fmaxf(m_o, eo[t]), mn_a = fmaxf(m_a, ea[t]);
            float sc_o = __expf(m_o - mn_o), sc_a = __expf(m_a - mn_a);
            float w_o = __expf(eo[t] - mn_o), w_a = __expf(ea[t] - mn_a);
            ox = ox * sc_o + ho[t].x * w_o; oy = oy * sc_o + ho[t].y * w_o;
            ax = ax * sc_a + ha[t].x * w_a; ay = ay * sc_a + ha[t].y * w_a;
            den_o = den_o * sc_o + w_o;
            den_a = den_a * sc_a + w_a;
            m_o = mn_o; m_a = mn_a;
        }
    }
    float inv_o = 1.f / (den_o + 1e-16f);
    float inv_a = 1.f / (den_a + 1e-16f);
    int c = lane * 2;
    float2 out_o, out_a;
    out_o.x = prelu_f(ox * inv_o + b2[c], p2[c]);
    out_o.y = prelu_f(oy * inv_o + b2[c + 1], p2[c + 1]);
    out_a.x = prelu_f(ax * inv_a + b2[c], p2[c]);
    out_a.y = prelu_f(ay * inv_a + b2[c + 1], p2[c + 1]);
    *reinterpret_cast<float2*>(x2 + (size_t)n * C2 + c) = out_o;
    *reinterpret_cast<float2*>(x2 + (size_t)na * C2 + c) = out_a;

    atomicAdd(&s_o[c], out_o.x);
    atomicAdd(&s_o[c + 1], out_o.y);
    atomicAdd(&s_a[c], out_a.x);
    atomicAdd(&s_a[c + 1], out_a.y);
    __syncthreads();
    if (tid < 64) {
        atomicAdd(&sums[tid], s_o[tid]);
        atomicAdd(&sums[64 + tid], s_a[tid]);
    }
}

// ---------------- readout / discriminator weights / adversarial vector ----------------
__global__ void k_small(const float* __restrict__ sums, const float* __restrict__ mlp_W,
                        const float* __restrict__ mlp_b, const float* __restrict__ disc_W,
                        const float* __restrict__ adv_W, const float* __restrict__ adv_b,
                        float* __restrict__ small) {
    __shared__ float so[64], sa[64], hos[64], hosa[64];
    int j = threadIdx.x;
    so[j] = 1.f / (1.f + expf(-(sums[j] / (float)N_NODES)));
    sa[j] = 1.f / (1.f + expf(-(sums[64 + j] / (float)N_NODES)));
    __syncthreads();
    float h1v = mlp_b[j], h2v = mlp_b[j];
    for (int i = 0; i < 64; i++) {
        float w = mlp_W[i * 64 + j];
        h1v += so[i] * w;
        h2v += sa[i] * w;
    }
    hos[j] = h1v; hosa[j] = h2v;
    __syncthreads();
    float wc1 = 0.f, wc2 = 0.f, vv = 0.f;
    for (int k = 0; k < 64; k++) {
        float w = disc_W[j * 64 + k];
        wc1 += w * hos[k];
        wc2 += w * hosa[k];
        vv += adv_W[j * 64 + k];
    }
    small[j] = wc1;
    small[64 + j] = wc2;
    small[128 + j] = vv;
    if (j == 0) {
        float s = 0.f;
        for (int k = 0; k < 64; k++) s += adv_b[k];
        small[192] = s;
    }
}

// ---------------- per-node outputs ----------------
__global__ void k_nodefinal(const float* __restrict__ x2, const float* __restrict__ small,
                            const float* __restrict__ disc_b, float* __restrict__ out) {
    int n = (blockIdx.x * blockDim.x + threadIdx.x) >> 5;
    int lane = threadIdx.x & 31;
    if (n >= N_NODES) return;
    float2 xo = *reinterpret_cast<const float2*>(x2 + (size_t)n * C2 + lane * 2);
    float2 xa = *reinterpret_cast<const float2*>(x2 + (size_t)(N_NODES + n) * C2 + lane * 2);
    float2 w1 = *reinterpret_cast<const float2*>(small + lane * 2);
    float2 w2 = *reinterpret_cast<const float2*>(small + 64 + lane * 2);
    float2 w3 = *reinterpret_cast<const float2*>(small + 128 + lane * 2);
    float p0 = warp_sum(xo.x * w1.x + xo.y * w1.y);
    float p1 = warp_sum(xa.x * w1.x + xa.y * w1.y);
    float p2 = warp_sum(xa.x * w2.x + xa.y * w2.y);
    float p3 = warp_sum(xo.x * w2.x + xo.y * w2.y);
    float p4 = warp_sum(xo.x * w3.x + xo.y * w3.y);
    float p5 = warp_sum(xa.x * w3.x + xa.y * w3.y);
    if (lane == 0) {
        float db = disc_b[0];
        float badv = small[192];
        out[OFF_RET + 2 * n] = p0 + db;
        out[OFF_RET + 2 * n + 1] = p1 + db;
        out[OFF_RETA + 2 * n] = p2 + db;
        out[OFF_RETA + 2 * n + 1] = p3 + db;
        out[OFF_LOGITS + n] = p4 + badv;
        out[OFF_LOGITS + N_NODES + n] = p5 + badv;
    }
    *reinterpret_cast<float2*>(out + OFF_X2 + (size_t)n * C2 + lane * 2) = xo;
}

// ---------------- entity decoder heads: log, log1 ----------------
__global__ void k_entityfinal(const float* __restrict__ fh, const float* __restrict__ fW2,
                              const float* __restrict__ fb2, const float* __restrict__ fW3,
                              const float* __restrict__ fb3, float* __restrict__ out) {
    int b = (blockIdx.x * blockDim.x + threadIdx.x) >> 5;
    int lane = threadIdx.x & 31;
    if (b >= BATCH) return;
    float a2x = 0.f, a2y = 0.f, a3x = 0.f, a3y = 0.f;
    for (int i = lane; i < DEC; i += 32) {
        float v = fh[(size_t)b * DEC + i];
        a2x += v * fW2[i * 2];
        a2y += v * fW2[i * 2 + 1];
        a3x += v * fW3[i * 2];
        a3y += v * fW3[i * 2 + 1];
    }
    a2x = warp_sum(a2x); a2y = warp_sum(a2y);
    a3x = warp_sum(a3x); a3y = warp_sum(a3y);
    if (lane == 0) {
        out[OFF_LOG + 2 * b] = a2x + fb2[0];
        out[OFF_LOG + 2 * b + 1] = a2y + fb2[1];
        out[OFF_LOG1 + 2 * b] = a3x + fb3[0];
        out[OFF_LOG1 + 2 * b + 1] = a3y + fb3[1];
    }
}

// ---------------- host launch ----------------
extern "C" void kernel_launch(void* const* d_in, const int* in_sizes, int n_in,
                              void* d_out, int out_size) {
    const float* x_o    = (const float*)d_in[0];
    const float* x_a    = (const float*)d_in[1];
    const int*   ei     = (const int*)d_in[2];
    const int*   idx    = (const int*)d_in[3];
    const float* W1     = (const float*)d_in[4];
    const float* a_src1 = (const float*)d_in[5];
    const float* a_dst1 = (const float*)d_in[6];
    const float* b1     = (const float*)d_in[7];
    const float* p1     = (const float*)d_in[8];
    const float* W2     = (const float*)d_in[9];
    const float* a_src2 = (const float*)d_in[10];
    const float* a_dst2 = (const float*)d_in[11];
    const float* b2     = (const float*)d_in[12];
    const float* p2     = (const float*)d_in[13];
    const float* mlp_W  = (const float*)d_in[14];
    const float* mlp_b  = (const float*)d_in[15];
    const float* disc_W = (const float*)d_in[16];
    const float* disc_b = (const float*)d_in[17];
    const float* adv_W  = (const float*)d_in[18];
    const float* adv_b  = (const float*)d_in[19];
    const float* f_W1   = (const float*)d_in[20];
    const float* f_b1   = (const float*)d_in[21];
    const float* f_W2   = (const float*)d_in[22];
    const float* f_b2   = (const float*)d_in[23];
    const float* f_W3   = (const float*)d_in[24];
    const float* f_b3   = (const float*)d_in[25];

    const int* e_src = ei;
    const int* e_dst = ei + N_EDGES;
    const int* idx0 = idx;
    const int* idx1 = idx + BATCH;

    __half *h1, *h2, *x1;
    float *x2, *as1, *ad1, *as2, *ad2, *sums, *small, *fh;
    int *cnt, *off, *cur, *csr, *bsum, *bpre;
    __nv_bfloat16 *whi, *wlo;
    cudaGetSymbolAddress((void**)&h1, g_h1);
    cudaGetSymbolAddress((void**)&x1, g_x1);
    cudaGetSymbolAddress((void**)&h2, g_h2);
    cudaGetSymbolAddress((void**)&x2, g_x2);
    cudaGetSymbolAddress((void**)&as1, g_as1);
    cudaGetSymbolAddress((void**)&ad1, g_ad1);
    cudaGetSymbolAddress((void**)&as2, g_as2);
    cudaGetSymbolAddress((void**)&ad2, g_ad2);
    cudaGetSymbolAddress((void**)&sums, g_sums);
    cudaGetSymbolAddress((void**)&small, g_small);
    cudaGetSymbolAddress((void**)&fh, g_fh);
    cudaGetSymbolAddress((void**)&cnt, g_cnt);
    cudaGetSymbolAddress((void**)&off, g_off);
    cudaGetSymbolAddress((void**)&cur, g_cur);
    cudaGetSymbolAddress((void**)&csr, g_csr);
    cudaGetSymbolAddress((void**)&bsum, g_bsum);
    cudaGetSymbolAddress((void**)&bpre, g_bpre);
    cudaGetSymbolAddress((void**)&whi, g_whi);
    cudaGetSymbolAddress((void**)&wlo, g_wlo);

    float* out = (float*)d_out;

    constexpr int SMEM_128 = 8 * (128 * 40 + 32 * 136);   // 75776
    constexpr int SMEM_64  = 8 * (128 * 40 + 32 * 72);    // 59392

    static cudaStream_t s1 = nullptr;
    static cudaEvent_t evFork = nullptr, evCsr = nullptr, evX2 = nullptr, evFus = nullptr;
    static bool init_done = false;
    if (!init_done) {
        cudaFuncSetAttribute(k_mma_gemm<128, 2, 4, 1, 1, 1, 0>,
                             cudaFuncAttributeMaxDynamicSharedMemorySize, SMEM_128);
        cudaFuncSetAttribute(k_mma_gemm<64, 8, 1, 0, 2, 1, 1>,
                             cudaFuncAttributeMaxDynamicSharedMemorySize, SMEM_64);
        cudaFuncSetAttribute(k_mma_gemm<128, 2, 4, 2, 0, 0, 0>,
                             cudaFuncAttributeMaxDynamicSharedMemorySize, SMEM_128);
        cudaStreamCreateWithFlags(&s1, cudaStreamNonBlocking);
        cudaEventCreateWithFlags(&evFork, cudaEventDisableTiming);
        cudaEventCreateWithFlags(&evCsr, cudaEventDisableTiming);
        cudaEventCreateWithFlags(&evX2, cudaEventDisableTiming);
        cudaEventCreateWithFlags(&evFus, cudaEventDisableTiming);
        init_done = true;
    }

    constexpr int SCAN_BLOCKS = (N_NODES + 1023) / 1024;   // 49
    const int M2 = 2 * N_NODES;
    const int gemmBlocksY = (M2 + 127) / 128;

    // launch 1 (main): weight pre-split
    k_splitW<<<(WSPLIT_TOTAL + 255) / 256, 256>>>(W1, W2, f_W1, whi, wlo);

    // fork side stream for CSR build
    cudaEventRecord(evFork, 0);
    cudaStreamWaitEvent(s1, evFork, 0);

    // launches 2-5 (s1): CSR chain, part 1
    k_zero<<<(N_NODES + 255) / 256, 256, 0, s1>>>(cnt, sums);
    k_hist<<<(N_EDGES + 255) / 256, 256, 0, s1>>>(e_dst, cnt);
    k_scanA<<<SCAN_BLOCKS, 1024, 0, s1>>>(cnt, off, bsum);
    k_scanB<<<1, 64, 0, s1>>>(bsum, bpre, off, SCAN_BLOCKS);

    // launch 6 (main): layer 1 GEMM (fp16 out) + fused attention-logit epilogue
    k_mma_gemm<128, 2, 4, 1, 1, 1, 0><<<dim3(1, gemmBlocksY), 256, SMEM_128>>>(
        x_o, x_a, whi + WOFF_W1, wlo + WOFF_W1, nullptr, h1, M2, C1, D_IN, N_NODES,
        nullptr, nullptr, a_src1, a_dst1, as1, ad1);

    // launches 7-8 (s1): CSR chain, part 2
    k_scanC<<<SCAN_BLOCKS, 1024, 0, s1>>>(off, cur, bpre);
    k_fill<<<(N_EDGES + 255) / 256, 256, 0, s1>>>(e_src, e_dst, cur, csr);
    cudaEventRecord(evCsr, s1);

    // join: agg1 needs CSR + GEMM1
    cudaStreamWaitEvent(0, evCsr, 0);
    k_agg1<<<N_NODES / 8, 256>>>(h1, as1, ad1, b1, p1, x1, off, csr);

    // layer 2 GEMM (fp16 in, fp16 out) + fused attention-logit epilogue
    k_mma_gemm<64, 8, 1, 0, 2, 1, 1><<<dim3(1, gemmBlocksY), 256, SMEM_64>>>(
        x1, nullptr, whi + WOFF_W2, wlo + WOFF_W2, nullptr, h2, M2, C2, C1, 0,
        nullptr, nullptr, a_src2, a_dst2, as2, ad2);

    k_agg2<<<N_NODES / 8, 256>>>(h2, as2, ad2, b2, p2, x2, off, csr, sums);

    // ---- fork after x2: fusion decoder on s1, readout heads on main ----
    cudaEventRecord(evX2, 0);
    cudaStreamWaitEvent(s1, evX2, 0);

    // s1: fusion decoder + entity heads (OFF_LOG / OFF_LOG1 regions)
    k_mma_gemm<128, 2, 4, 2, 0, 0, 0><<<dim3(DEC / 128, BATCH / 128), 256, SMEM_128, s1>>>(
        x2, nullptr, whi + WOFF_FW1, wlo + WOFF_FW1, f_b1, fh, BATCH, DEC, 2 * C2, 0,
        idx0, idx1, nullptr, nullptr, nullptr, nullptr);
    k_entityfinal<<<(BATCH + 7) / 8, 256, 0, s1>>>(fh, f_W2, f_b2, f_W3, f_b3, out);
    cudaEventRecord(evFus, s1);

    // main: readout + per-node heads (RET/RETA/X2/LOGITS regions)
    k_small<<<1, 64>>>(sums, mlp_W, mlp_b, disc_W, adv_W, adv_b, small);
    k_nodefinal<<<(N_NODES + 7) / 8, 256>>>(x2, small, disc_b, out);

    // join before returning to harness
    cudaStreamWaitEvent(0, evFus, 0);
}

// round 11
// speedup vs baseline: 1.0337x; 1.0337x over previous
#include <cuda_runtime.h>
#include <cuda_bf16.h>
#include <cuda_fp16.h>
#include <cstdint>
#include <math.h>

// ---------------- problem constants ----------------
static constexpr int N_NODES = 50000;
static constexpr int N_EDGES = 400000;
static constexpr int D_IN    = 256;
static constexpr int C1      = 128;   // HEADS*H1
static constexpr int C2      = 64;    // H2
static constexpr int BATCH   = 4096;
static constexpr int DEC     = 512;

// output layout (tuple flattened in order)
static constexpr int OFF_LOG    = 0;
static constexpr int OFF_RET    = OFF_LOG + BATCH * 2;          // 8192
static constexpr int OFF_RETA   = OFF_RET + N_NODES * 2;        // 108192
static constexpr int OFF_X2     = OFF_RETA + N_NODES * 2;       // 208192
static constexpr int OFF_LOGITS = OFF_X2 + N_NODES * C2;        // 3408192
static constexpr int OFF_LOG1   = OFF_LOGITS + 2 * N_NODES;     // 3508192

// weight-split offsets (elements)
static constexpr int WOFF_W1  = 0;                  // 256*128 = 32768
static constexpr int WOFF_W2  = 32768;              // 128*64  = 8192
static constexpr int WOFF_FW1 = 40960;              // 128*512 = 65536
static constexpr int WSPLIT_TOTAL = 106496;

// ---------------- device scratch ----------------
__device__ __half  g_h1[2 * N_NODES * C1];
__device__ __half  g_x1[2 * N_NODES * C1];
__device__ __half  g_h2[2 * N_NODES * C2];
__device__ float   g_x2[2 * N_NODES * C2];
// interleaved logit layouts: as1/ad1 = [node][8] (o heads 0-3, a heads 4-7)
//                            as2/ad2 = [node][2] (o, a)
__device__ float   g_as1[N_NODES * 8];
__device__ float   g_ad1[N_NODES * 8];
__device__ float   g_as2[N_NODES * 2];
__device__ float   g_ad2[N_NODES * 2];
__device__ int     g_cnt[N_NODES];
__device__ int     g_off[N_NODES + 1];
__device__ int     g_cur[N_NODES];
__device__ int     g_csr[N_EDGES];
__device__ int     g_bsum[64];
__device__ int     g_bpre[64];
__device__ float   g_sums[128];
__device__ float   g_small[200];
__device__ float   g_fh[BATCH * DEC];
__device__ __nv_bfloat16 g_whi[WSPLIT_TOTAL];
__device__ __nv_bfloat16 g_wlo[WSPLIT_TOTAL];

// ---------------- helpers ----------------
__device__ __forceinline__ float leaky02(float x) { return x >= 0.f ? x : 0.2f * x; }
__device__ __forceinline__ float prelu_f(float x, float w) { return x >= 0.f ? x : w * x; }
__device__ __forceinline__ float warp_sum(float v) {
#pragma unroll
    for (int o = 16; o > 0; o >>= 1) v += __shfl_xor_sync(0xffffffffu, v, o);
    return v;
}
__device__ __forceinline__ float quad_sum(float v) {
    v += __shfl_xor_sync(0xffffffffu, v, 1);
    v += __shfl_xor_sync(0xffffffffu, v, 2);
    return v;
}
__device__ __forceinline__ unsigned smem_u32(const void* p) {
    return (unsigned)__cvta_generic_to_shared(p);
}
__device__ __forceinline__ float4 ldh4(const __half* p) {
    uint2 u = *reinterpret_cast<const uint2*>(p);
    float2 a = __half22float2(*reinterpret_cast<__half2*>(&u.x));
    float2 b = __half22float2(*reinterpret_cast<__half2*>(&u.y));
    return make_float4(a.x, a.y, b.x, b.y);
}
__device__ __forceinline__ float2 ldh2(const __half* p) {
    __half2 h = *reinterpret_cast<const __half2*>(p);
    return __half22float2(h);
}
__device__ __forceinline__ void sth4(__half* p, float4 v) {
    uint2 u;
    __half2 a = __floats2half2_rn(v.x, v.y);
    __half2 b = __floats2half2_rn(v.z, v.w);
    u.x = *reinterpret_cast<unsigned*>(&a);
    u.y = *reinterpret_cast<unsigned*>(&b);
    *reinterpret_cast<uint2*>(p) = u;
}

// ---------------- tensor-core primitives ----------------
__device__ __forceinline__ void ldm_x4(unsigned r[4], unsigned addr) {
    asm volatile("ldmatrix.sync.aligned.m8n8.x4.shared.b16 {%0,%1,%2,%3}, [%4];"
                 : "=r"(r[0]), "=r"(r[1]), "=r"(r[2]), "=r"(r[3]) : "r"(addr));
}
__device__ __forceinline__ void ldm_x2t(unsigned r[2], unsigned addr) {
    asm volatile("ldmatrix.sync.aligned.m8n8.x2.trans.shared.b16 {%0,%1}, [%2];"
                 : "=r"(r[0]), "=r"(r[1]) : "r"(addr));
}
__device__ __forceinline__ void mma_bf16(float d[4], const unsigned a[4], const unsigned b[2]) {
    asm volatile("mma.sync.aligned.m16n8k16.row.col.f32.bf16.bf16.f32 "
                 "{%0,%1,%2,%3},{%4,%5,%6,%7},{%8,%9},{%0,%1,%2,%3};"
                 : "+f"(d[0]), "+f"(d[1]), "+f"(d[2]), "+f"(d[3])
                 : "r"(a[0]), "r"(a[1]), "r"(a[2]), "r"(a[3]), "r"(b[0]), "r"(b[1]));
}

// split fp32 -> bf16 hi + bf16 lo, store 4 values (8B) to each smem buffer
__device__ __forceinline__ void store_split(__nv_bfloat16* hi, __nv_bfloat16* lo, float4 v) {
    __nv_bfloat16 h0 = __float2bfloat16(v.x), h1 = __float2bfloat16(v.y),
                  h2 = __float2bfloat16(v.z), h3 = __float2bfloat16(v.w);
    __nv_bfloat16 l0 = __float2bfloat16(v.x - __bfloat162float(h0)),
                  l1 = __float2bfloat16(v.y - __bfloat162float(h1)),
                  l2 = __float2bfloat16(v.z - __bfloat162float(h2)),
                  l3 = __float2bfloat16(v.w - __bfloat162float(h3));
    __nv_bfloat162 hp0 = __halves2bfloat162(h0, h1), hp1 = __halves2bfloat162(h2, h3);
    __nv_bfloat162 lp0 = __halves2bfloat162(l0, l1), lp1 = __halves2bfloat162(l2, l3);
    *reinterpret_cast<uint2*>(hi) =
        make_uint2(*reinterpret_cast<unsigned*>(&hp0), *reinterpret_cast<unsigned*>(&hp1));
    *reinterpret_cast<uint2*>(lo) =
        make_uint2(*reinterpret_cast<unsigned*>(&lp0), *reinterpret_cast<unsigned*>(&lp1));
}

// ---------------- weight pre-split (once per launch) ----------------
__global__ void k_splitW(const float* __restrict__ W1, const float* __restrict__ W2,
                         const float* __restrict__ fW1, __nv_bfloat16* __restrict__ hi,
                         __nv_bfloat16* __restrict__ lo) {
    int i = blockIdx.x * 256 + threadIdx.x;
    if (i >= WSPLIT_TOTAL) return;
    float v;
    if (i < WOFF_W2) v = W1[i];
    else if (i < WOFF_FW1) v = W2[i - WOFF_W2];
    else v = fW1[i - WOFF_FW1];
    __nv_bfloat16 h = __float2bfloat16(v);
    hi[i] = h;
    lo[i] = __float2bfloat16(v - __bfloat162float(h));
}

// ---------------- split-bf16 tensor-core GEMM: C = A @ B (pre-split bf16 B) ----------------
// MODE 0: A = A0 direct. MODE 1: row<Msplit from A0 else A1. MODE 2: gather via idx0/idx1,
//         epilogue bias+relu.
// EPI 0: none. EPI 1: 4-head x 32-col dots -> interleaved [node][8] (WTN==32, needs Msplit).
// EPI 2: 1-head x 64-col dots -> interleaved [node][2] (WTN==64, needs Msplit).
// OUTC 0: fp32 C. OUTC 1: fp16 C.   INA 0: fp32 A. INA 1: fp16 A.
template <int BN, int WM, int WN, int MODE, int EPI, int OUTC, int INA>
__global__ void __launch_bounds__(256)
k_mma_gemm(const void* __restrict__ A0v, const void* __restrict__ A1v,
           const __nv_bfloat16* __restrict__ BhiG, const __nv_bfloat16* __restrict__ BloG,
           const float* __restrict__ bias, void* __restrict__ Cout,
           int M, int N, int K, int Msplit,
           const int* __restrict__ idx0, const int* __restrict__ idx1,
           const float* __restrict__ asrc, const float* __restrict__ adst,
           float* __restrict__ as_out, float* __restrict__ ad_out) {
    constexpr int BM = 128, BK = 32;
    constexpr int APAD = BK + 8;
    constexpr int BPAD = BN + 8;
    constexpr int WTM = BM / WM, WTN = BN / WN;
    constexpr int MT = WTM / 16, NT = WTN / 8;
    constexpr int A_ITERS = BM * BK / 1024;
    constexpr int B_IT = (BK * BN) / 2048;
    constexpr int ASZ = BM * APAD;
    constexpr int BSZ = BK * BPAD;

    extern __shared__ __align__(16) char dynsmem[];
    __nv_bfloat16* Ahi = reinterpret_cast<__nv_bfloat16*>(dynsmem);
    __nv_bfloat16* Alo = Ahi + 2 * ASZ;
    __nv_bfloat16* Bhi = Alo + 2 * ASZ;
    __nv_bfloat16* Blo = Bhi + 2 * BSZ;

    const int tid = threadIdx.x, lane = tid & 31, warp = tid >> 5;
    const int wy = warp / WN, wx = warp % WN;
    const int row0 = blockIdx.y * BM, col0 = blockIdx.x * BN;

    float acc[MT][NT][4];
#pragma unroll
    for (int i = 0; i < MT; i++)
#pragma unroll
        for (int j = 0; j < NT; j++)
#pragma unroll
            for (int q = 0; q < 4; q++) acc[i][j][q] = 0.f;

    float4 aReg[A_ITERS];
    uint4 bRegH[B_IT], bRegL[B_IT];

    auto loadTiles = [&](int k0) {
#pragma unroll
        for (int it = 0; it < A_ITERS; it++) {
            int idx = tid + it * 256;
            int r = idx >> 3, c = (idx & 7) << 2;
            int gr = row0 + r;
            float4 v = make_float4(0.f, 0.f, 0.f, 0.f);
            if (MODE == 2) {
                int node = (k0 < C2) ? idx0[gr] : idx1[gr];
                int kc = (k0 & (C2 - 1)) + c;
                v = *reinterpret_cast<const float4*>((const float*)A0v + (size_t)node * C2 + kc);
            } else if (gr < M) {
                if (INA == 1) {
                    v = ldh4((const __half*)A0v + (size_t)gr * K + k0 + c);
                } else {
                    const float* Ap;
                    if (MODE == 1)
                        Ap = (gr < Msplit) ? (const float*)A0v + (size_t)gr * K
                                           : (const float*)A1v + (size_t)(gr - Msplit) * K;
                    else
                        Ap = (const float*)A0v + (size_t)gr * K;
                    v = *reinterpret_cast<const float4*>(Ap + k0 + c);
                }
            }
            aReg[it] = v;
        }
#pragma unroll
        for (int it = 0; it < B_IT; it++) {
            int idx = tid + it * 256;
            int r = idx / (BN / 8), c = (idx % (BN / 8)) * 8;
            size_t g = (size_t)(k0 + r) * N + col0 + c;
            bRegH[it] = *reinterpret_cast<const uint4*>(BhiG + g);
            bRegL[it] = *reinterpret_cast<const uint4*>(BloG + g);
        }
    };

    auto storeTiles = [&](int buf) {
#pragma unroll
        for (int it = 0; it < A_ITERS; it++) {
            int idx = tid + it * 256;
            int r = idx >> 3, c = (idx & 7) << 2;
            store_split(&Ahi[buf * ASZ + r * APAD + c], &Alo[buf * ASZ + r * APAD + c], aReg[it]);
        }
#pragma unroll
        for (int it = 0; it < B_IT; it++) {
            int idx = tid + it * 256;
            int r = idx / (BN / 8), c = (idx % (BN / 8)) * 8;
            *reinterpret_cast<uint4*>(&Bhi[buf * BSZ + r * BPAD + c]) = bRegH[it];
            *reinterpret_cast<uint4*>(&Blo[buf * BSZ + r * BPAD + c]) = bRegL[it];
        }
    };

    const int nT = K / BK;
    loadTiles(0);
    storeTiles(0);
    __syncthreads();

    for (int t = 0; t < nT; t++) {
        int cur = t & 1;
        if (t + 1 < nT) loadTiles((t + 1) * BK);
#pragma unroll
        for (int ks = 0; ks < 2; ks++) {
            unsigned ah[MT][4], al[MT][4];
#pragma unroll
            for (int i = 0; i < MT; i++) {
                int arow = wy * WTM + i * 16 + (lane & 15);
                int acol = ks * 16 + ((lane >> 4) << 3);
                ldm_x4(ah[i], smem_u32(&Ahi[cur * ASZ + arow * APAD + acol]));
                ldm_x4(al[i], smem_u32(&Alo[cur * ASZ + arow * APAD + acol]));
            }
#pragma unroll
            for (int j = 0; j < NT; j++) {
                int brow = ks * 16 + (lane & 15);
                int bcol = wx * WTN + j * 8;
                unsigned bh[2], bl[2];
                ldm_x2t(bh, smem_u32(&Bhi[cur * BSZ + brow * BPAD + bcol]));
                ldm_x2t(bl, smem_u32(&Blo[cur * BSZ + brow * BPAD + bcol]));
#pragma unroll
                for (int i = 0; i < MT; i++) {
                    mma_bf16(acc[i][j], ah[i], bh);
                    mma_bf16(acc[i][j], ah[i], bl);
                    mma_bf16(acc[i][j], al[i], bh);
                }
            }
        }
        if (t + 1 < nT) storeTiles(cur ^ 1);
        __syncthreads();
    }

    // --- C store ---
#pragma unroll
    for (int i = 0; i < MT; i++) {
        int rg = row0 + wy * WTM + i * 16 + (lane >> 2);
#pragma unroll
        for (int j = 0; j < NT; j++) {
            int cg = col0 + wx * WTN + j * 8 + (lane & 3) * 2;
            float2 v0 = make_float2(acc[i][j][0], acc[i][j][1]);
            float2 v1 = make_float2(acc[i][j][2], acc[i][j][3]);
            if (MODE == 2) {
                float b0 = bias[cg], b1 = bias[cg + 1];
                v0.x = fmaxf(v0.x + b0, 0.f); v0.y = fmaxf(v0.y + b1, 0.f);
                v1.x = fmaxf(v1.x + b0, 0.f); v1.y = fmaxf(v1.y + b1, 0.f);
            }
            if (OUTC == 1) {
                __half* C = (__half*)Cout;
                if (rg < M)
                    *reinterpret_cast<__half2*>(C + (size_t)rg * N + cg) = __floats2half2_rn(v0.x, v0.y);
                if (rg + 8 < M)
                    *reinterpret_cast<__half2*>(C + (size_t)(rg + 8) * N + cg) = __floats2half2_rn(v1.x, v1.y);
            } else {
                float* C = (float*)Cout;
                if (rg < M)
                    *reinterpret_cast<float2*>(C + (size_t)rg * N + cg) = v0;
                if (rg + 8 < M)
                    *reinterpret_cast<float2*>(C + (size_t)(rg + 8) * N + cg) = v1;
            }
        }
    }

    // --- fused attention-logit epilogue (interleaved layouts) ---
    if (EPI != 0) {
        const int head = (EPI == 1) ? wx : 0;
        float2 ws[NT], wd[NT];
#pragma unroll
        for (int j = 0; j < NT; j++) {
            int f = head * 32 + j * 8 + (lane & 3) * 2;
            ws[j] = *reinterpret_cast<const float2*>(asrc + f);
            wd[j] = *reinterpret_cast<const float2*>(adst + f);
        }
#pragma unroll
        for (int i = 0; i < MT; i++) {
            float ds0 = 0.f, dd0 = 0.f, ds1 = 0.f, dd1 = 0.f;
#pragma unroll
            for (int j = 0; j < NT; j++) {
                ds0 += acc[i][j][0] * ws[j].x + acc[i][j][1] * ws[j].y;
                ds1 += acc[i][j][2] * ws[j].x + acc[i][j][3] * ws[j].y;
                dd0 += acc[i][j][0] * wd[j].x + acc[i][j][1] * wd[j].y;
                dd1 += acc[i][j][2] * wd[j].x + acc[i][j][3] * wd[j].y;
            }
            ds0 = quad_sum(ds0); ds1 = quad_sum(ds1);
            dd0 = quad_sum(dd0); dd1 = quad_sum(dd1);
            if ((lane & 3) == 0) {
                int r0 = row0 + wy * WTM + i * 16 + (lane >> 2);
#pragma unroll
                for (int q = 0; q < 2; q++) {
                    int r = r0 + q * 8;
                    if (r >= M) continue;
                    float ds = q ? ds1 : ds0, dd = q ? dd1 : dd0;
                    int node = (r < Msplit) ? r : r - Msplit;
                    if (EPI == 1) {
                        int o8 = (r < Msplit) ? 0 : 4;
                        as_out[(size_t)node * 8 + o8 + head] = ds;
                        ad_out[(size_t)node * 8 + o8 + head] = dd;
                    } else {
                        int o2 = (r < Msplit) ? 0 : 1;
                        as_out[(size_t)node * 2 + o2] = ds;
                        ad_out[(size_t)node * 2 + o2] = dd;
                    }
                }
            }
        }
    }
}

// ---------------- CSR build ----------------
__global__ void k_zero(int* cnt, float* sums) {
    int i = blockIdx.x * blockDim.x + threadIdx.x;
    if (i < N_NODES) cnt[i] = 0;
    if (i < 128) sums[i] = 0.f;
}

__global__ void k_hist(const int* __restrict__ dst, int* __restrict__ cnt) {
    int e = blockIdx.x * blockDim.x + threadIdx.x;
    if (e < N_EDGES) atomicAdd(&cnt[dst[e]], 1);
}

// two-level scan
__global__ void k_scanA(const int* __restrict__ cnt, int* __restrict__ off,
                        int* __restrict__ bsum) {
    __shared__ int ws[32];
    int i = blockIdx.x * 1024 + threadIdx.x;
    int lane = threadIdx.x & 31, wid = threadIdx.x >> 5;
    int v = (i < N_NODES) ? cnt[i] : 0;
    int x = v;
#pragma unroll
    for (int o = 1; o < 32; o <<= 1) {
        int t = __shfl_up_sync(0xffffffffu, x, o);
        if (lane >= o) x += t;
    }
    if (lane == 31) ws[wid] = x;
    __syncthreads();
    if (wid == 0) {
        int w = ws[lane];
#pragma unroll
        for (int o = 1; o < 32; o <<= 1) {
            int t = __shfl_up_sync(0xffffffffu, w, o);
            if (lane >= o) w += t;
        }
        ws[lane] = w;
    }
    __syncthreads();
    int incl = x + (wid > 0 ? ws[wid - 1] : 0);
    if (i < N_NODES) off[i] = incl - v;
    if (threadIdx.x == 1023) bsum[blockIdx.x] = incl;
}

__global__ void k_scanB(const int* __restrict__ bsum, int* __restrict__ bpre,
                        int* __restrict__ off, int nblocks) {
    __shared__ int s[64];
    int tid = threadIdx.x;
    int v = (tid < nblocks) ? bsum[tid] : 0;
    s[tid] = v;
    __syncthreads();
    for (int o = 1; o < 64; o <<= 1) {
        int t = (tid >= o) ? s[tid - o] : 0;
        __syncthreads();
        s[tid] += t;
        __syncthreads();
    }
    bpre[tid] = s[tid] - v;
    if (tid == 63) off[N_NODES] = s[63];
}

__global__ void k_scanC(int* __restrict__ off, int* __restrict__ cur,
                        const int* __restrict__ bpre) {
    int i = blockIdx.x * 1024 + threadIdx.x;
    if (i < N_NODES) {
        int t = off[i] + bpre[blockIdx.x];
        off[i] = t;
        cur[i] = t;
    }
}

__global__ void k_fill(const int* __restrict__ src, const int* __restrict__ dst,
                       int* __restrict__ cur, int* __restrict__ csr) {
    int e = blockIdx.x * blockDim.x + threadIdx.x;
    if (e < N_EDGES) {
        int d = dst[e];
        int p = atomicAdd(&cur[d], 1);
        csr[p] = src[e];
    }
}

// ---------------- GAT aggregation layer 1 (online softmax, interleaved logits) ------------
__global__ void k_agg1(const __half* __restrict__ h1, const float* __restrict__ as_,
                       const float* __restrict__ ad_, const float* __restrict__ b1,
                       const float* __restrict__ p1, __half* __restrict__ x1,
                       const int* __restrict__ off, const int* __restrict__ csr) {
    int n = (blockIdx.x * blockDim.x + threadIdx.x) >> 5;
    int lane = threadIdx.x & 31;
    if (n >= N_NODES) return;
    int na = n + N_NODES;
    int h = lane >> 3;
    float adh_o = ad_[(size_t)n * 8 + h];
    float adh_a = ad_[(size_t)n * 8 + 4 + h];
    int beg = off[n], end = off[n + 1];

    float m_o = leaky02(as_[(size_t)n * 8 + h] + adh_o);
    float m_a = leaky02(as_[(size_t)n * 8 + 4 + h] + adh_a);
    float den_o = 1.f, den_a = 1.f;
    float4 v_o = ldh4(h1 + (size_t)n * C1 + lane * 4);
    float4 v_a = ldh4(h1 + (size_t)na * C1 + lane * 4);
    float ox = v_o.x, oy = v_o.y, oz = v_o.z, ow = v_o.w;
    float ax = v_a.x, ay = v_a.y, az = v_a.z, aw = v_a.w;

    for (int j = beg; j < end; j++) {
        int s = csr[j];
        float e_o = leaky02(as_[(size_t)s * 8 + h] + adh_o);
        float e_a = leaky02(as_[(size_t)s * 8 + 4 + h] + adh_a);
        float mn_o = fmaxf(m_o, e_o), mn_a = fmaxf(m_a, e_a);
        float sc_o = __expf(m_o - mn_o), sc_a = __expf(m_a - mn_a);
        float w_o = __expf(e_o - mn_o), w_a = __expf(e_a - mn_a);
        float4 ho = ldh4(h1 + (size_t)s * C1 + lane * 4);
        float4 ha = ldh4(h1 + (size_t)(s + N_NODES) * C1 + lane * 4);
        ox = ox * sc_o + ho.x * w_o; oy = oy * sc_o + ho.y * w_o;
        oz = oz * sc_o + ho.z * w_o; ow = ow * sc_o + ho.w * w_o;
        ax = ax * sc_a + ha.x * w_a; ay = ay * sc_a + ha.y * w_a;
        az = az * sc_a + ha.z * w_a; aw = aw * sc_a + ha.w * w_a;
        den_o = den_o * sc_o + w_o;
        den_a = den_a * sc_a + w_a;
        m_o = mn_o; m_a = mn_a;
    }
    float inv_o = 1.f / (den_o + 1e-16f);
    float inv_a = 1.f / (den_a + 1e-16f);
    int c = lane * 4;
    float4 bb = *reinterpret_cast<const float4*>(b1 + c);
    float4 pp = *reinterpret_cast<const float4*>(p1 + c);
    float4 out_o, out_a;
    out_o.x = prelu_f(ox * inv_o + bb.x, pp.x);
    out_o.y = prelu_f(oy * inv_o + bb.y, pp.y);
    out_o.z = prelu_f(oz * inv_o + bb.z, pp.z);
    out_o.w = prelu_f(ow * inv_o + bb.w, pp.w);
    out_a.x = prelu_f(ax * inv_a + bb.x, pp.x);
    out_a.y = prelu_f(ay * inv_a + bb.y, pp.y);
    out_a.z = prelu_f(az * inv_a + bb.z, pp.z);
    out_a.w = prelu_f(aw * inv_a + bb.w, pp.w);
    sth4(x1 + (size_t)n * C1 + c, out_o);
    sth4(x1 + (size_t)na * C1 + c, out_a);
}

// ---------------- GAT aggregation layer 2 (online softmax, interleaved, fused colsum) -----
__global__ void k_agg2(const __half* __restrict__ h2, const float* __restrict__ as_,
                       const float* __restrict__ ad_, const float* __restrict__ b2,
                       const float* __restrict__ p2, float* __restrict__ x2,
                       const int* __restrict__ off, const int* __restrict__ csr,
                       float* __restrict__ sums) {
    __shared__ float s_o[64], s_a[64];
    int tid = threadIdx.x;
    int n = (blockIdx.x * blockDim.x + tid) >> 5;
    int lane = tid & 31;
    if (tid < 64) { s_o[tid] = 0.f; s_a[tid] = 0.f; }
    __syncthreads();

    int na = n + N_NODES;
    float2 adp = *reinterpret_cast<const float2*>(ad_ + (size_t)n * 2);
    float adh_o = adp.x, adh_a = adp.y;
    int beg = off[n], end = off[n + 1];

    float2 asp = *reinterpret_cast<const float2*>(as_ + (size_t)n * 2);
    float m_o = leaky02(asp.x + adh_o);
    float m_a = leaky02(asp.y + adh_a);
    float den_o = 1.f, den_a = 1.f;
    float2 v_o = ldh2(h2 + (size_t)n * C2 + lane * 2);
    float2 v_a = ldh2(h2 + (size_t)na * C2 + lane * 2);
    float ox = v_o.x, oy = v_o.y, ax = v_a.x, ay = v_a.y;

    for (int j = beg; j < end; j++) {
        int s = csr[j];
        float2 ep = *reinterpret_cast<const float2*>(as_ + (size_t)s * 2);
        float e_o = leaky02(ep.x + adh_o);
        float e_a = leaky02(ep.y + adh_a);
        float mn_o = fmaxf(m_o, e_o), mn_a = fmaxf(m_a, e_a);
        float sc_o = __expf(m_o - mn_o), sc_a = __expf(m_a - mn_a);
        float w_o = __expf(e_o - mn_o), w_a = __expf(e_a - mn_a);
        float2 ho = ldh2(h2 + (size_t)s * C2 + lane * 2);
        float2 ha = ldh2(h2 + (size_t)(s + N_NODES) * C2 + lane * 2);
        ox = ox * sc_o + ho.x * w_o; oy = oy * sc_o + ho.y * w_o;
        ax = ax * sc_a + ha.x * w_a; ay = ay * sc_a + ha.y * w_a;
        den_o = den_o * sc_o + w_o;
        den_a = den_a * sc_a + w_a;
        m_o = mn_o; m_a = mn_a;
    }
    float inv_o = 1.f / (den_o + 1e-16f);
    float inv_a = 1.f / (den_a + 1e-16f);
    int c = lane * 2;
    float2 out_o, out_a;
    out_o.x = prelu_f(ox * inv_o + b2[c], p2[c]);
    out_o.y = prelu_f(oy * inv_o + b2[c + 1], p2[c + 1]);
    out_a.x = prelu_f(ax * inv_a + b2[c], p2[c]);
    out_a.y = prelu_f(ay * inv_a + b2[c + 1], p2[c + 1]);
    *reinterpret_cast<float2*>(x2 + (size_t)n * C2 + c) = out_o;
    *reinterpret_cast<float2*>(x2 + (size_t)na * C2 + c) = out_a;

    atomicAdd(&s_o[c], out_o.x);
    atomicAdd(&s_o[c + 1], out_o.y);
    atomicAdd(&s_a[c], out_a.x);
    atomicAdd(&s_a[c + 1], out_a.y);
    __syncthreads();
    if (tid < 64) {
        atomicAdd(&sums[tid], s_o[tid]);
        atomicAdd(&sums[64 + tid], s_a[tid]);
    }
}

// ---------------- readout / discriminator weights / adversarial vector ----------------
__global__ void k_small(const float* __restrict__ sums, const float* __restrict__ mlp_W,
                        const float* __restrict__ mlp_b, const float* __restrict__ disc_W,
                        const float* __restrict__ adv_W, const float* __restrict__ adv_b,
                        float* __restrict__ small) {
    __shared__ float so[64], sa[64], hos[64], hosa[64];
    int j = threadIdx.x;
    so[j] = 1.f / (1.f + expf(-(sums[j] / (float)N_NODES)));
    sa[j] = 1.f / (1.f + expf(-(sums[64 + j] / (float)N_NODES)));
    __syncthreads();
    float h1v = mlp_b[j], h2v = mlp_b[j];
    for (int i = 0; i < 64; i++) {
        float w = mlp_W[i * 64 + j];
        h1v += so[i] * w;
        h2v += sa[i] * w;
    }
    hos[j] = h1v; hosa[j] = h2v;
    __syncthreads();
    float wc1 = 0.f, wc2 = 0.f, vv = 0.f;
    for (int k = 0; k < 64; k++) {
        float w = disc_W[j * 64 + k];
        wc1 += w * hos[k];
        wc2 += w * hosa[k];
        vv += adv_W[j * 64 + k];
    }
    small[j] = wc1;
    small[64 + j] = wc2;
    small[128 + j] = vv;
    if (j == 0) {
        float s = 0.f;
        for (int k = 0; k < 64; k++) s += adv_b[k];
        small[192] = s;
    }
}

// ---------------- per-node outputs ----------------
__global__ void k_nodefinal(const float* __restrict__ x2, const float* __restrict__ small,
                            const float* __restrict__ disc_b, float* __restrict__ out) {
    int n = (blockIdx.x * blockDim.x + threadIdx.x) >> 5;
    int lane = threadIdx.x & 31;
    if (n >= N_NODES) return;
    float2 xo = *reinterpret_cast<const float2*>(x2 + (size_t)n * C2 + lane * 2);
    float2 xa = *reinterpret_cast<const float2*>(x2 + (size_t)(N_NODES + n) * C2 + lane * 2);
    float2 w1 = *reinterpret_cast<const float2*>(small + lane * 2);
    float2 w2 = *reinterpret_cast<const float2*>(small + 64 + lane * 2);
    float2 w3 = *reinterpret_cast<const float2*>(small + 128 + lane * 2);
    float p0 = warp_sum(xo.x * w1.x + xo.y * w1.y);
    float p1 = warp_sum(xa.x * w1.x + xa.y * w1.y);
    float p2 = warp_sum(xa.x * w2.x + xa.y * w2.y);
    float p3 = warp_sum(xo.x * w2.x + xo.y * w2.y);
    float p4 = warp_sum(xo.x * w3.x + xo.y * w3.y);
    float p5 = warp_sum(xa.x * w3.x + xa.y * w3.y);
    if (lane == 0) {
        float db = disc_b[0];
        float badv = small[192];
        out[OFF_RET + 2 * n] = p0 + db;
        out[OFF_RET + 2 * n + 1] = p1 + db;
        out[OFF_RETA + 2 * n] = p2 + db;
        out[OFF_RETA + 2 * n + 1] = p3 + db;
        out[OFF_LOGITS + n] = p4 + badv;
        out[OFF_LOGITS + N_NODES + n] = p5 + badv;
    }
    *reinterpret_cast<float2*>(out + OFF_X2 + (size_t)n * C2 + lane * 2) = xo;
}

// ---------------- entity decoder heads: log, log1 ----------------
__global__ void k_entityfinal(const float* __restrict__ fh, const float* __restrict__ fW2,
                              const float* __restrict__ fb2, const float* __restrict__ fW3,
                              const float* __restrict__ fb3, float* __restrict__ out) {
    int b = (blockIdx.x * blockDim.x + threadIdx.x) >> 5;
    int lane = threadIdx.x & 31;
    if (b >= BATCH) return;
    float a2x = 0.f, a2y = 0.f, a3x = 0.f, a3y = 0.f;
    for (int i = lane; i < DEC; i += 32) {
        float v = fh[(size_t)b * DEC + i];
        a2x += v * fW2[i * 2];
        a2y += v * fW2[i * 2 + 1];
        a3x += v * fW3[i * 2];
        a3y += v * fW3[i * 2 + 1];
    }
    a2x = warp_sum(a2x); a2y = warp_sum(a2y);
    a3x = warp_sum(a3x); a3y = warp_sum(a3y);
    if (lane == 0) {
        out[OFF_LOG + 2 * b] = a2x + fb2[0];
        out[OFF_LOG + 2 * b + 1] = a2y + fb2[1];
        out[OFF_LOG1 + 2 * b] = a3x + fb3[0];
        out[OFF_LOG1 + 2 * b + 1] = a3y + fb3[1];
    }
}

// ---------------- host launch ----------------
extern "C" void kernel_launch(void* const* d_in, const int* in_sizes, int n_in,
                              void* d_out, int out_size) {
    const float* x_o    = (const float*)d_in[0];
    const float* x_a    = (const float*)d_in[1];
    const int*   ei     = (const int*)d_in[2];
    const int*   idx    = (const int*)d_in[3];
    const float* W1     = (const float*)d_in[4];
    const float* a_src1 = (const float*)d_in[5];
    const float* a_dst1 = (const float*)d_in[6];
    const float* b1     = (const float*)d_in[7];
    const float* p1     = (const float*)d_in[8];
    const float* W2     = (const float*)d_in[9];
    const float* a_src2 = (const float*)d_in[10];
    const float* a_dst2 = (const float*)d_in[11];
    const float* b2     = (const float*)d_in[12];
    const float* p2     = (const float*)d_in[13];
    const float* mlp_W  = (const float*)d_in[14];
    const float* mlp_b  = (const float*)d_in[15];
    const float* disc_W = (const float*)d_in[16];
    const float* disc_b = (const float*)d_in[17];
    const float* adv_W  = (const float*)d_in[18];
    const float* adv_b  = (const float*)d_in[19];
    const float* f_W1   = (const float*)d_in[20];
    const float* f_b1   = (const float*)d_in[21];
    const float* f_W2   = (const float*)d_in[22];
    const float* f_b2   = (const float*)d_in[23];
    const float* f_W3   = (const float*)d_in[24];
    const float* f_b3   = (const float*)d_in[25];

    const int* e_src = ei;
    const int* e_dst = ei + N_EDGES;
    const int* idx0 = idx;
    const int* idx1 = idx + BATCH;

    __half *h1, *h2, *x1;
    float *x2, *as1, *ad1, *as2, *ad2, *sums, *small, *fh;
    int *cnt, *off, *cur, *csr, *bsum, *bpre;
    __nv_bfloat16 *whi, *wlo;
    cudaGetSymbolAddress((void**)&h1, g_h1);
    cudaGetSymbolAddress((void**)&x1, g_x1);
    cudaGetSymbolAddress((void**)&h2, g_h2);
    cudaGetSymbolAddress((void**)&x2, g_x2);
    cudaGetSymbolAddress((void**)&as1, g_as1);
    cudaGetSymbolAddress((void**)&ad1, g_ad1);
    cudaGetSymbolAddress((void**)&as2, g_as2);
    cudaGetSymbolAddress((void**)&ad2, g_ad2);
    cudaGetSymbolAddress((void**)&sums, g_sums);
    cudaGetSymbolAddress((void**)&small, g_small);
    cudaGetSymbolAddress((void**)&fh, g_fh);
    cudaGetSymbolAddress((void**)&cnt, g_cnt);
    cudaGetSymbolAddress((void**)&off, g_off);
    cudaGetSymbolAddress((void**)&cur, g_cur);
    cudaGetSymbolAddress((void**)&csr, g_csr);
    cudaGetSymbolAddress((void**)&bsum, g_bsum);
    cudaGetSymbolAddress((void**)&bpre, g_bpre);
    cudaGetSymbolAddress((void**)&whi, g_whi);
    cudaGetSymbolAddress((void**)&wlo, g_wlo);

    float* out = (float*)d_out;

    constexpr int SMEM_128 = 8 * (128 * 40 + 32 * 136);   // 75776
    constexpr int SMEM_64  = 8 * (128 * 40 + 32 * 72);    // 59392

    static cudaStream_t s1 = nullptr;
    static cudaEvent_t evFork = nullptr, evCsr = nullptr, evX2 = nullptr, evFus = nullptr;
    static bool init_done = false;
    if (!init_done) {
        cudaFuncSetAttribute(k_mma_gemm<128, 2, 4, 1, 1, 1, 0>,
                             cudaFuncAttributeMaxDynamicSharedMemorySize, SMEM_128);
        cudaFuncSetAttribute(k_mma_gemm<64, 8, 1, 0, 2, 1, 1>,
                             cudaFuncAttributeMaxDynamicSharedMemorySize, SMEM_64);
        cudaFuncSetAttribute(k_mma_gemm<128, 2, 4, 2, 0, 0, 0>,
                             cudaFuncAttributeMaxDynamicSharedMemorySize, SMEM_128);
        cudaStreamCreateWithFlags(&s1, cudaStreamNonBlocking);
        cudaEventCreateWithFlags(&evFork, cudaEventDisableTiming);
        cudaEventCreateWithFlags(&evCsr, cudaEventDisableTiming);
        cudaEventCreateWithFlags(&evX2, cudaEventDisableTiming);
        cudaEventCreateWithFlags(&evFus, cudaEventDisableTiming);
        init_done = true;
    }

    constexpr int SCAN_BLOCKS = (N_NODES + 1023) / 1024;   // 49
    const int M2 = 2 * N_NODES;
    const int gemmBlocksY = (M2 + 127) / 128;

    // launch 1 (main): weight pre-split
    k_splitW<<<(WSPLIT_TOTAL + 255) / 256, 256>>>(W1, W2, f_W1, whi, wlo);

    // fork side stream for CSR build
    cudaEventRecord(evFork, 0);
    cudaStreamWaitEvent(s1, evFork, 0);

    // launches 2-3 (s1): CSR chain, part 1
    k_zero<<<(N_NODES + 255) / 256, 256, 0, s1>>>(cnt, sums);
    k_hist<<<(N_EDGES + 255) / 256, 256, 0, s1>>>(e_dst, cnt);

    // launch 4 (main): layer 1 GEMM (fp16 out) + fused attention-logit epilogue [ncu target]
    k_mma_gemm<128, 2, 4, 1, 1, 1, 0><<<dim3(1, gemmBlocksY), 256, SMEM_128>>>(
        x_o, x_a, whi + WOFF_W1, wlo + WOFF_W1, nullptr, h1, M2, C1, D_IN, N_NODES,
        nullptr, nullptr, a_src1, a_dst1, as1, ad1);

    // launches 5-8 (s1): CSR chain, part 2
    k_scanA<<<SCAN_BLOCKS, 1024, 0, s1>>>(cnt, off, bsum);
    k_scanB<<<1, 64, 0, s1>>>(bsum, bpre, off, SCAN_BLOCKS);
    k_scanC<<<SCAN_BLOCKS, 1024, 0, s1>>>(off, cur, bpre);
    k_fill<<<(N_EDGES + 255) / 256, 256, 0, s1>>>(e_src, e_dst, cur, csr);
    cudaEventRecord(evCsr, s1);

    // join: agg1 needs CSR + GEMM1
    cudaStreamWaitEvent(0, evCsr, 0);
    k_agg1<<<N_NODES / 8, 256>>>(h1, as1, ad1, b1, p1, x1, off, csr);

    // layer 2 GEMM (fp16 in, fp16 out) + fused attention-logit epilogue
    k_mma_gemm<64, 8, 1, 0, 2, 1, 1><<<dim3(1, gemmBlocksY), 256, SMEM_64>>>(
        x1, nullptr, whi + WOFF_W2, wlo + WOFF_W2, nullptr, h2, M2, C2, C1, N_NODES,
        nullptr, nullptr, a_src2, a_dst2, as2, ad2);

    k_agg2<<<N_NODES / 8, 256>>>(h2, as2, ad2, b2, p2, x2, off, csr, sums);

    // ---- fork after x2: fusion decoder on s1, readout heads on main ----
    cudaEventRecord(evX2, 0);
    cudaStreamWaitEvent(s1, evX2, 0);

    // s1: fusion decoder + entity heads (OFF_LOG / OFF_LOG1 regions)
    k_mma_gemm<128, 2, 4, 2, 0, 0, 0><<<dim3(DEC / 128, BATCH / 128), 256, SMEM_128, s1>>>(
        x2, nullptr, whi + WOFF_FW1, wlo + WOFF_FW1, f_b1, fh, BATCH, DEC, 2 * C2, 0,
        idx0, idx1, nullptr, nullptr, nullptr, nullptr);
    k_entityfinal<<<(BATCH + 7) / 8, 256, 0, s1>>>(fh, f_W2, f_b2, f_W3, f_b3, out);
    cudaEventRecord(evFus, s1);

    // main: readout + per-node heads (RET/RETA/X2/LOGITS regions)
    k_small<<<1, 64>>>(sums, mlp_W, mlp_b, disc_W, adv_W, adv_b, small);
    k_nodefinal<<<(N_NODES + 7) / 8, 256>>>(x2, small, disc_b, out);

    // join before returning to harness
    cudaStreamWaitEvent(0, evFus, 0);
}

// round 12
// speedup vs baseline: 1.0917x; 1.0560x over previous
#include <cuda_runtime.h>
#include <cuda_bf16.h>
#include <cuda_fp16.h>
#include <cstdint>
#include <math.h>

// ---------------- problem constants ----------------
static constexpr int N_NODES = 50000;
static constexpr int N_EDGES = 400000;
static constexpr int D_IN    = 256;
static constexpr int C1      = 128;   // HEADS*H1
static constexpr int C2      = 64;    // H2
static constexpr int BATCH   = 4096;
static constexpr int DEC     = 512;

// output layout (tuple flattened in order)
static constexpr int OFF_LOG    = 0;
static constexpr int OFF_RET    = OFF_LOG + BATCH * 2;          // 8192
static constexpr int OFF_RETA   = OFF_RET + N_NODES * 2;        // 108192
static constexpr int OFF_X2     = OFF_RETA + N_NODES * 2;       // 208192
static constexpr int OFF_LOGITS = OFF_X2 + N_NODES * C2;        // 3408192
static constexpr int OFF_LOG1   = OFF_LOGITS + 2 * N_NODES;     // 3508192

// weight-split offsets (elements)
static constexpr int WOFF_W1  = 0;                  // 256*128 = 32768
static constexpr int WOFF_W2  = 32768;              // 128*64  = 8192
static constexpr int WOFF_FW1 = 40960;              // 128*512 = 65536
static constexpr int WSPLIT_TOTAL = 106496;

// ---------------- device scratch ----------------
__device__ __half  g_h1[2 * N_NODES * C1];
__device__ __half  g_x1[2 * N_NODES * C1];
__device__ __half  g_h2[2 * N_NODES * C2];
__device__ float   g_x2[2 * N_NODES * C2];
// interleaved logit layouts: as1/ad1 = [node][8] (o heads 0-3, a heads 4-7)
//                            as2/ad2 = [node][2] (o, a)
__device__ float   g_as1[N_NODES * 8];
__device__ float   g_ad1[N_NODES * 8];
__device__ float   g_as2[N_NODES * 2];
__device__ float   g_ad2[N_NODES * 2];
__device__ int     g_cnt[N_NODES];
__device__ int     g_off[N_NODES + 1];
__device__ int     g_cur[N_NODES];
__device__ int     g_csr[N_EDGES];
__device__ int     g_bsum[64];
__device__ int     g_bpre[64];
__device__ float   g_sums[128];
__device__ float   g_small[200];
__device__ float   g_fh[BATCH * DEC];
__device__ __nv_bfloat16 g_whi[WSPLIT_TOTAL];
__device__ __nv_bfloat16 g_wlo[WSPLIT_TOTAL];

// ---------------- helpers ----------------
__device__ __forceinline__ float leaky02(float x) { return x >= 0.f ? x : 0.2f * x; }
__device__ __forceinline__ float prelu_f(float x, float w) { return x >= 0.f ? x : w * x; }
__device__ __forceinline__ float warp_sum(float v) {
#pragma unroll
    for (int o = 16; o > 0; o >>= 1) v += __shfl_xor_sync(0xffffffffu, v, o);
    return v;
}
__device__ __forceinline__ float quad_sum(float v) {
    v += __shfl_xor_sync(0xffffffffu, v, 1);
    v += __shfl_xor_sync(0xffffffffu, v, 2);
    return v;
}
__device__ __forceinline__ unsigned smem_u32(const void* p) {
    return (unsigned)__cvta_generic_to_shared(p);
}
__device__ __forceinline__ float4 ldh4(const __half* p) {
    uint2 u = *reinterpret_cast<const uint2*>(p);
    float2 a = __half22float2(*reinterpret_cast<__half2*>(&u.x));
    float2 b = __half22float2(*reinterpret_cast<__half2*>(&u.y));
    return make_float4(a.x, a.y, b.x, b.y);
}
__device__ __forceinline__ float2 ldh2(const __half* p) {
    __half2 h = *reinterpret_cast<const __half2*>(p);
    return __half22float2(h);
}
__device__ __forceinline__ void sth4(__half* p, float4 v) {
    uint2 u;
    __half2 a = __floats2half2_rn(v.x, v.y);
    __half2 b = __floats2half2_rn(v.z, v.w);
    u.x = *reinterpret_cast<unsigned*>(&a);
    u.y = *reinterpret_cast<unsigned*>(&b);
    *reinterpret_cast<uint2*>(p) = u;
}

// ---------------- tensor-core primitives ----------------
__device__ __forceinline__ void ldm_x4(unsigned r[4], unsigned addr) {
    asm volatile("ldmatrix.sync.aligned.m8n8.x4.shared.b16 {%0,%1,%2,%3}, [%4];"
                 : "=r"(r[0]), "=r"(r[1]), "=r"(r[2]), "=r"(r[3]) : "r"(addr));
}
__device__ __forceinline__ void ldm_x2t(unsigned r[2], unsigned addr) {
    asm volatile("ldmatrix.sync.aligned.m8n8.x2.trans.shared.b16 {%0,%1}, [%2];"
                 : "=r"(r[0]), "=r"(r[1]) : "r"(addr));
}
__device__ __forceinline__ void mma_bf16(float d[4], const unsigned a[4], const unsigned b[2]) {
    asm volatile("mma.sync.aligned.m16n8k16.row.col.f32.bf16.bf16.f32 "
                 "{%0,%1,%2,%3},{%4,%5,%6,%7},{%8,%9},{%0,%1,%2,%3};"
                 : "+f"(d[0]), "+f"(d[1]), "+f"(d[2]), "+f"(d[3])
                 : "r"(a[0]), "r"(a[1]), "r"(a[2]), "r"(a[3]), "r"(b[0]), "r"(b[1]));
}

// split fp32 -> bf16 hi + bf16 lo, store 4 values (8B) to each smem buffer
__device__ __forceinline__ void store_split(__nv_bfloat16* hi, __nv_bfloat16* lo, float4 v) {
    __nv_bfloat16 h0 = __float2bfloat16(v.x), h1 = __float2bfloat16(v.y),
                  h2 = __float2bfloat16(v.z), h3 = __float2bfloat16(v.w);
    __nv_bfloat16 l0 = __float2bfloat16(v.x - __bfloat162float(h0)),
                  l1 = __float2bfloat16(v.y - __bfloat162float(h1)),
                  l2 = __float2bfloat16(v.z - __bfloat162float(h2)),
                  l3 = __float2bfloat16(v.w - __bfloat162float(h3));
    __nv_bfloat162 hp0 = __halves2bfloat162(h0, h1), hp1 = __halves2bfloat162(h2, h3);
    __nv_bfloat162 lp0 = __halves2bfloat162(l0, l1), lp1 = __halves2bfloat162(l2, l3);
    *reinterpret_cast<uint2*>(hi) =
        make_uint2(*reinterpret_cast<unsigned*>(&hp0), *reinterpret_cast<unsigned*>(&hp1));
    *reinterpret_cast<uint2*>(lo) =
        make_uint2(*reinterpret_cast<unsigned*>(&lp0), *reinterpret_cast<unsigned*>(&lp1));
}

// ---------------- weight pre-split (once per launch) ----------------
__global__ void k_splitW(const float* __restrict__ W1, const float* __restrict__ W2,
                         const float* __restrict__ fW1, __nv_bfloat16* __restrict__ hi,
                         __nv_bfloat16* __restrict__ lo) {
    int i = blockIdx.x * 256 + threadIdx.x;
    if (i >= WSPLIT_TOTAL) return;
    float v;
    if (i < WOFF_W2) v = W1[i];
    else if (i < WOFF_FW1) v = W2[i - WOFF_W2];
    else v = fW1[i - WOFF_FW1];
    __nv_bfloat16 h = __float2bfloat16(v);
    hi[i] = h;
    lo[i] = __float2bfloat16(v - __bfloat162float(h));
}

// ---------------- split-bf16 tensor-core GEMM: C = A @ B (pre-split bf16 B) ----------------
// BM/BN tile, WM x WN warp grid (8 warps, 256 threads). Double-buffered dyn smem.
// MODE 0: A = A0 direct. MODE 1: row<Msplit from A0 else A1. MODE 2: gather via idx0/idx1,
//         epilogue bias+relu.
// EPI 0: none. EPI 1: 4-head x 32-col dots -> interleaved [node][8] (WTN==32, needs Msplit).
// EPI 2: 1-head x 64-col dots -> interleaved [node][2] (WTN==64, needs Msplit).
// OUTC 0: fp32 C. OUTC 1: fp16 C.   INA 0: fp32 A. INA 1: fp16 A.
template <int BM, int BN, int WM, int WN, int MODE, int EPI, int OUTC, int INA>
__global__ void __launch_bounds__(256)
k_mma_gemm(const void* __restrict__ A0v, const void* __restrict__ A1v,
           const __nv_bfloat16* __restrict__ BhiG, const __nv_bfloat16* __restrict__ BloG,
           const float* __restrict__ bias, void* __restrict__ Cout,
           int M, int N, int K, int Msplit,
           const int* __restrict__ idx0, const int* __restrict__ idx1,
           const float* __restrict__ asrc, const float* __restrict__ adst,
           float* __restrict__ as_out, float* __restrict__ ad_out) {
    constexpr int BK = 32;
    constexpr int APAD = BK + 8;
    constexpr int BPAD = BN + 8;
    constexpr int WTM = BM / WM, WTN = BN / WN;
    constexpr int MT = WTM / 16, NT = WTN / 8;
    constexpr int A_ITERS = BM * BK / 1024;
    constexpr int B_IT = (BK * BN) / 2048;
    constexpr int ASZ = BM * APAD;
    constexpr int BSZ = BK * BPAD;

    extern __shared__ __align__(16) char dynsmem[];
    __nv_bfloat16* Ahi = reinterpret_cast<__nv_bfloat16*>(dynsmem);
    __nv_bfloat16* Alo = Ahi + 2 * ASZ;
    __nv_bfloat16* Bhi = Alo + 2 * ASZ;
    __nv_bfloat16* Blo = Bhi + 2 * BSZ;

    const int tid = threadIdx.x, lane = tid & 31, warp = tid >> 5;
    const int wy = warp / WN, wx = warp % WN;
    const int row0 = blockIdx.y * BM, col0 = blockIdx.x * BN;

    float acc[MT][NT][4];
#pragma unroll
    for (int i = 0; i < MT; i++)
#pragma unroll
        for (int j = 0; j < NT; j++)
#pragma unroll
            for (int q = 0; q < 4; q++) acc[i][j][q] = 0.f;

    float4 aReg[A_ITERS];
    uint4 bRegH[B_IT], bRegL[B_IT];

    auto loadTiles = [&](int k0) {
#pragma unroll
        for (int it = 0; it < A_ITERS; it++) {
            int idx = tid + it * 256;
            int r = idx >> 3, c = (idx & 7) << 2;
            int gr = row0 + r;
            float4 v = make_float4(0.f, 0.f, 0.f, 0.f);
            if (MODE == 2) {
                int node = (k0 < C2) ? idx0[gr] : idx1[gr];
                int kc = (k0 & (C2 - 1)) + c;
                v = *reinterpret_cast<const float4*>((const float*)A0v + (size_t)node * C2 + kc);
            } else if (gr < M) {
                if (INA == 1) {
                    v = ldh4((const __half*)A0v + (size_t)gr * K + k0 + c);
                } else {
                    const float* Ap;
                    if (MODE == 1)
                        Ap = (gr < Msplit) ? (const float*)A0v + (size_t)gr * K
                                           : (const float*)A1v + (size_t)(gr - Msplit) * K;
                    else
                        Ap = (const float*)A0v + (size_t)gr * K;
                    v = *reinterpret_cast<const float4*>(Ap + k0 + c);
                }
            }
            aReg[it] = v;
        }
#pragma unroll
        for (int it = 0; it < B_IT; it++) {
            int idx = tid + it * 256;
            int r = idx / (BN / 8), c = (idx % (BN / 8)) * 8;
            size_t g = (size_t)(k0 + r) * N + col0 + c;
            bRegH[it] = *reinterpret_cast<const uint4*>(BhiG + g);
            bRegL[it] = *reinterpret_cast<const uint4*>(BloG + g);
        }
    };

    auto storeTiles = [&](int buf) {
#pragma unroll
        for (int it = 0; it < A_ITERS; it++) {
            int idx = tid + it * 256;
            int r = idx >> 3, c = (idx & 7) << 2;
            store_split(&Ahi[buf * ASZ + r * APAD + c], &Alo[buf * ASZ + r * APAD + c], aReg[it]);
        }
#pragma unroll
        for (int it = 0; it < B_IT; it++) {
            int idx = tid + it * 256;
            int r = idx / (BN / 8), c = (idx % (BN / 8)) * 8;
            *reinterpret_cast<uint4*>(&Bhi[buf * BSZ + r * BPAD + c]) = bRegH[it];
            *reinterpret_cast<uint4*>(&Blo[buf * BSZ + r * BPAD + c]) = bRegL[it];
        }
    };

    const int nT = K / BK;
    loadTiles(0);
    storeTiles(0);
    __syncthreads();

    for (int t = 0; t < nT; t++) {
        int cur = t & 1;
        if (t + 1 < nT) loadTiles((t + 1) * BK);
#pragma unroll
        for (int ks = 0; ks < 2; ks++) {
            unsigned ah[MT][4], al[MT][4];
#pragma unroll
            for (int i = 0; i < MT; i++) {
                int arow = wy * WTM + i * 16 + (lane & 15);
                int acol = ks * 16 + ((lane >> 4) << 3);
                ldm_x4(ah[i], smem_u32(&Ahi[cur * ASZ + arow * APAD + acol]));
                ldm_x4(al[i], smem_u32(&Alo[cur * ASZ + arow * APAD + acol]));
            }
#pragma unroll
            for (int j = 0; j < NT; j++) {
                int brow = ks * 16 + (lane & 15);
                int bcol = wx * WTN + j * 8;
                unsigned bh[2], bl[2];
                ldm_x2t(bh, smem_u32(&Bhi[cur * BSZ + brow * BPAD + bcol]));
                ldm_x2t(bl, smem_u32(&Blo[cur * BSZ + brow * BPAD + bcol]));
#pragma unroll
                for (int i = 0; i < MT; i++) {
                    mma_bf16(acc[i][j], ah[i], bh);
                    mma_bf16(acc[i][j], ah[i], bl);
                    mma_bf16(acc[i][j], al[i], bh);
                }
            }
        }
        if (t + 1 < nT) storeTiles(cur ^ 1);
        __syncthreads();
    }

    // --- C store ---
#pragma unroll
    for (int i = 0; i < MT; i++) {
        int rg = row0 + wy * WTM + i * 16 + (lane >> 2);
#pragma unroll
        for (int j = 0; j < NT; j++) {
            int cg = col0 + wx * WTN + j * 8 + (lane & 3) * 2;
            float2 v0 = make_float2(acc[i][j][0], acc[i][j][1]);
            float2 v1 = make_float2(acc[i][j][2], acc[i][j][3]);
            if (MODE == 2) {
                float b0 = bias[cg], b1 = bias[cg + 1];
                v0.x = fmaxf(v0.x + b0, 0.f); v0.y = fmaxf(v0.y + b1, 0.f);
                v1.x = fmaxf(v1.x + b0, 0.f); v1.y = fmaxf(v1.y + b1, 0.f);
            }
            if (OUTC == 1) {
                __half* C = (__half*)Cout;
                if (rg < M)
                    *reinterpret_cast<__half2*>(C + (size_t)rg * N + cg) = __floats2half2_rn(v0.x, v0.y);
                if (rg + 8 < M)
                    *reinterpret_cast<__half2*>(C + (size_t)(rg + 8) * N + cg) = __floats2half2_rn(v1.x, v1.y);
            } else {
                float* C = (float*)Cout;
                if (rg < M)
                    *reinterpret_cast<float2*>(C + (size_t)rg * N + cg) = v0;
                if (rg + 8 < M)
                    *reinterpret_cast<float2*>(C + (size_t)(rg + 8) * N + cg) = v1;
            }
        }
    }

    // --- fused attention-logit epilogue (interleaved layouts) ---
    if (EPI != 0) {
        const int head = (EPI == 1) ? wx : 0;
        float2 ws[NT], wd[NT];
#pragma unroll
        for (int j = 0; j < NT; j++) {
            int f = head * 32 + j * 8 + (lane & 3) * 2;
            ws[j] = *reinterpret_cast<const float2*>(asrc + f);
            wd[j] = *reinterpret_cast<const float2*>(adst + f);
        }
#pragma unroll
        for (int i = 0; i < MT; i++) {
            float ds0 = 0.f, dd0 = 0.f, ds1 = 0.f, dd1 = 0.f;
#pragma unroll
            for (int j = 0; j < NT; j++) {
                ds0 += acc[i][j][0] * ws[j].x + acc[i][j][1] * ws[j].y;
                ds1 += acc[i][j][2] * ws[j].x + acc[i][j][3] * ws[j].y;
                dd0 += acc[i][j][0] * wd[j].x + acc[i][j][1] * wd[j].y;
                dd1 += acc[i][j][2] * wd[j].x + acc[i][j][3] * wd[j].y;
            }
            ds0 = quad_sum(ds0); ds1 = quad_sum(ds1);
            dd0 = quad_sum(dd0); dd1 = quad_sum(dd1);
            if ((lane & 3) == 0) {
                int r0 = row0 + wy * WTM + i * 16 + (lane >> 2);
#pragma unroll
                for (int q = 0; q < 2; q++) {
                    int r = r0 + q * 8;
                    if (r >= M) continue;
                    float ds = q ? ds1 : ds0, dd = q ? dd1 : dd0;
                    int node = (r < Msplit) ? r : r - Msplit;
                    if (EPI == 1) {
                        int o8 = (r < Msplit) ? 0 : 4;
                        as_out[(size_t)node * 8 + o8 + head] = ds;
                        ad_out[(size_t)node * 8 + o8 + head] = dd;
                    } else {
                        int o2 = (r < Msplit) ? 0 : 1;
                        as_out[(size_t)node * 2 + o2] = ds;
                        ad_out[(size_t)node * 2 + o2] = dd;
                    }
                }
            }
        }
    }
}

// ---------------- CSR build ----------------
__global__ void k_zero(int* cnt, float* sums) {
    int i = blockIdx.x * blockDim.x + threadIdx.x;
    if (i < N_NODES) cnt[i] = 0;
    if (i < 128) sums[i] = 0.f;
}

__global__ void k_hist(const int* __restrict__ dst, int* __restrict__ cnt) {
    int e = blockIdx.x * blockDim.x + threadIdx.x;
    if (e < N_EDGES) atomicAdd(&cnt[dst[e]], 1);
}

// two-level scan
__global__ void k_scanA(const int* __restrict__ cnt, int* __restrict__ off,
                        int* __restrict__ bsum) {
    __shared__ int ws[32];
    int i = blockIdx.x * 1024 + threadIdx.x;
    int lane = threadIdx.x & 31, wid = threadIdx.x >> 5;
    int v = (i < N_NODES) ? cnt[i] : 0;
    int x = v;
#pragma unroll
    for (int o = 1; o < 32; o <<= 1) {
        int t = __shfl_up_sync(0xffffffffu, x, o);
        if (lane >= o) x += t;
    }
    if (lane == 31) ws[wid] = x;
    __syncthreads();
    if (wid == 0) {
        int w = ws[lane];
#pragma unroll
        for (int o = 1; o < 32; o <<= 1) {
            int t = __shfl_up_sync(0xffffffffu, w, o);
            if (lane >= o) w += t;
        }
        ws[lane] = w;
    }
    __syncthreads();
    int incl = x + (wid > 0 ? ws[wid - 1] : 0);
    if (i < N_NODES) off[i] = incl - v;
    if (threadIdx.x == 1023) bsum[blockIdx.x] = incl;
}

__global__ void k_scanB(const int* __restrict__ bsum, int* __restrict__ bpre,
                        int* __restrict__ off, int nblocks) {
    __shared__ int s[64];
    int tid = threadIdx.x;
    int v = (tid < nblocks) ? bsum[tid] : 0;
    s[tid] = v;
    __syncthreads();
    for (int o = 1; o < 64; o <<= 1) {
        int t = (tid >= o) ? s[tid - o] : 0;
        __syncthreads();
        s[tid] += t;
        __syncthreads();
    }
    bpre[tid] = s[tid] - v;
    if (tid == 63) off[N_NODES] = s[63];
}

__global__ void k_scanC(int* __restrict__ off, int* __restrict__ cur,
                        const int* __restrict__ bpre) {
    int i = blockIdx.x * 1024 + threadIdx.x;
    if (i < N_NODES) {
        int t = off[i] + bpre[blockIdx.x];
        off[i] = t;
        cur[i] = t;
    }
}

__global__ void k_fill(const int* __restrict__ src, const int* __restrict__ dst,
                       int* __restrict__ cur, int* __restrict__ csr) {
    int e = blockIdx.x * blockDim.x + threadIdx.x;
    if (e < N_EDGES) {
        int d = dst[e];
        int p = atomicAdd(&cur[d], 1);
        csr[p] = src[e];
    }
}

// ---------------- GAT aggregation layer 1 (online softmax, interleaved logits) ------------
__global__ void k_agg1(const __half* __restrict__ h1, const float* __restrict__ as_,
                       const float* __restrict__ ad_, const float* __restrict__ b1,
                       const float* __restrict__ p1, __half* __restrict__ x1,
                       const int* __restrict__ off, const int* __restrict__ csr) {
    int n = (blockIdx.x * blockDim.x + threadIdx.x) >> 5;
    int lane = threadIdx.x & 31;
    if (n >= N_NODES) return;
    int na = n + N_NODES;
    int h = lane >> 3;
    float adh_o = ad_[(size_t)n * 8 + h];
    float adh_a = ad_[(size_t)n * 8 + 4 + h];
    int beg = off[n], end = off[n + 1];

    float m_o = leaky02(as_[(size_t)n * 8 + h] + adh_o);
    float m_a = leaky02(as_[(size_t)n * 8 + 4 + h] + adh_a);
    float den_o = 1.f, den_a = 1.f;
    float4 v_o = ldh4(h1 + (size_t)n * C1 + lane * 4);
    float4 v_a = ldh4(h1 + (size_t)na * C1 + lane * 4);
    float ox = v_o.x, oy = v_o.y, oz = v_o.z, ow = v_o.w;
    float ax = v_a.x, ay = v_a.y, az = v_a.z, aw = v_a.w;

    for (int j = beg; j < end; j++) {
        int s = csr[j];
        float e_o = leaky02(as_[(size_t)s * 8 + h] + adh_o);
        float e_a = leaky02(as_[(size_t)s * 8 + 4 + h] + adh_a);
        float mn_o = fmaxf(m_o, e_o), mn_a = fmaxf(m_a, e_a);
        float sc_o = __expf(m_o - mn_o), sc_a = __expf(m_a - mn_a);
        float w_o = __expf(e_o - mn_o), w_a = __expf(e_a - mn_a);
        float4 ho = ldh4(h1 + (size_t)s * C1 + lane * 4);
        float4 ha = ldh4(h1 + (size_t)(s + N_NODES) * C1 + lane * 4);
        ox = ox * sc_o + ho.x * w_o; oy = oy * sc_o + ho.y * w_o;
        oz = oz * sc_o + ho.z * w_o; ow = ow * sc_o + ho.w * w_o;
        ax = ax * sc_a + ha.x * w_a; ay = ay * sc_a + ha.y * w_a;
        az = az * sc_a + ha.z * w_a; aw = aw * sc_a + ha.w * w_a;
        den_o = den_o * sc_o + w_o;
        den_a = den_a * sc_a + w_a;
        m_o = mn_o; m_a = mn_a;
    }
    float inv_o = 1.f / (den_o + 1e-16f);
    float inv_a = 1.f / (den_a + 1e-16f);
    int c = lane * 4;
    float4 bb = *reinterpret_cast<const float4*>(b1 + c);
    float4 pp = *reinterpret_cast<const float4*>(p1 + c);
    float4 out_o, out_a;
    out_o.x = prelu_f(ox * inv_o + bb.x, pp.x);
    out_o.y = prelu_f(oy * inv_o + bb.y, pp.y);
    out_o.z = prelu_f(oz * inv_o + bb.z, pp.z);
    out_o.w = prelu_f(ow * inv_o + bb.w, pp.w);
    out_a.x = prelu_f(ax * inv_a + bb.x, pp.x);
    out_a.y = prelu_f(ay * inv_a + bb.y, pp.y);
    out_a.z = prelu_f(az * inv_a + bb.z, pp.z);
    out_a.w = prelu_f(aw * inv_a + bb.w, pp.w);
    sth4(x1 + (size_t)n * C1 + c, out_o);
    sth4(x1 + (size_t)na * C1 + c, out_a);
}

// ---------------- GAT aggregation layer 2 (online softmax, interleaved, fused colsum) -----
__global__ void k_agg2(const __half* __restrict__ h2, const float* __restrict__ as_,
                       const float* __restrict__ ad_, const float* __restrict__ b2,
                       const float* __restrict__ p2, float* __restrict__ x2,
                       const int* __restrict__ off, const int* __restrict__ csr,
                       float* __restrict__ sums) {
    __shared__ float s_o[64], s_a[64];
    int tid = threadIdx.x;
    int n = (blockIdx.x * blockDim.x + tid) >> 5;
    int lane = tid & 31;
    if (tid < 64) { s_o[tid] = 0.f; s_a[tid] = 0.f; }
    __syncthreads();

    int na = n + N_NODES;
    float2 adp = *reinterpret_cast<const float2*>(ad_ + (size_t)n * 2);
    float adh_o = adp.x, adh_a = adp.y;
    int beg = off[n], end = off[n + 1];

    float2 asp = *reinterpret_cast<const float2*>(as_ + (size_t)n * 2);
    float m_o = leaky02(asp.x + adh_o);
    float m_a = leaky02(asp.y + adh_a);
    float den_o = 1.f, den_a = 1.f;
    float2 v_o = ldh2(h2 + (size_t)n * C2 + lane * 2);
    float2 v_a = ldh2(h2 + (size_t)na * C2 + lane * 2);
    float ox = v_o.x, oy = v_o.y, ax = v_a.x, ay = v_a.y;

    for (int j = beg; j < end; j++) {
        int s = csr[j];
        float2 ep = *reinterpret_cast<const float2*>(as_ + (size_t)s * 2);
        float e_o = leaky02(ep.x + adh_o);
        float e_a = leaky02(ep.y + adh_a);
        float mn_o = fmaxf(m_o, e_o), mn_a = fmaxf(m_a, e_a);
        float sc_o = __expf(m_o - mn_o), sc_a = __expf(m_a - mn_a);
        float w_o = __expf(e_o - mn_o), w_a = __expf(e_a - mn_a);
        float2 ho = ldh2(h2 + (size_t)s * C2 + lane * 2);
        float2 ha = ldh2(h2 + (size_t)(s + N_NODES) * C2 + lane * 2);
        ox = ox * sc_o + ho.x * w_o; oy = oy * sc_o + ho.y * w_o;
        ax = ax * sc_a + ha.x * w_a; ay = ay * sc_a + ha.y * w_a;
        den_o = den_o * sc_o + w_o;
        den_a = den_a * sc_a + w_a;
        m_o = mn_o; m_a = mn_a;
    }
    float inv_o = 1.f / (den_o + 1e-16f);
    float inv_a = 1.f / (den_a + 1e-16f);
    int c = lane * 2;
    float2 out_o, out_a;
    out_o.x = prelu_f(ox * inv_o + b2[c], p2[c]);
    out_o.y = prelu_f(oy * inv_o + b2[c + 1], p2[c + 1]);
    out_a.x = prelu_f(ax * inv_a + b2[c], p2[c]);
    out_a.y = prelu_f(ay * inv_a + b2[c + 1], p2[c + 1]);
    *reinterpret_cast<float2*>(x2 + (size_t)n * C2 + c) = out_o;
    *reinterpret_cast<float2*>(x2 + (size_t)na * C2 + c) = out_a;

    atomicAdd(&s_o[c], out_o.x);
    atomicAdd(&s_o[c + 1], out_o.y);
    atomicAdd(&s_a[c], out_a.x);
    atomicAdd(&s_a[c + 1], out_a.y);
    __syncthreads();
    if (tid < 64) {
        atomicAdd(&sums[tid], s_o[tid]);
        atomicAdd(&sums[64 + tid], s_a[tid]);
    }
}

// ---------------- readout / discriminator weights / adversarial vector ----------------
__global__ void k_small(const float* __restrict__ sums, const float* __restrict__ mlp_W,
                        const float* __restrict__ mlp_b, const float* __restrict__ disc_W,
                        const float* __restrict__ adv_W, const float* __restrict__ adv_b,
                        float* __restrict__ small) {
    __shared__ float so[64], sa[64], hos[64], hosa[64];
    int j = threadIdx.x;
    so[j] = 1.f / (1.f + expf(-(sums[j] / (float)N_NODES)));
    sa[j] = 1.f / (1.f + expf(-(sums[64 + j] / (float)N_NODES)));
    __syncthreads();
    float h1v = mlp_b[j], h2v = mlp_b[j];
    for (int i = 0; i < 64; i++) {
        float w = mlp_W[i * 64 + j];
        h1v += so[i] * w;
        h2v += sa[i] * w;
    }
    hos[j] = h1v; hosa[j] = h2v;
    __syncthreads();
    float wc1 = 0.f, wc2 = 0.f, vv = 0.f;
    for (int k = 0; k < 64; k++) {
        float w = disc_W[j * 64 + k];
        wc1 += w * hos[k];
        wc2 += w * hosa[k];
        vv += adv_W[j * 64 + k];
    }
    small[j] = wc1;
    small[64 + j] = wc2;
    small[128 + j] = vv;
    if (j == 0) {
        float s = 0.f;
        for (int k = 0; k < 64; k++) s += adv_b[k];
        small[192] = s;
    }
}

// ---------------- per-node outputs ----------------
__global__ void k_nodefinal(const float* __restrict__ x2, const float* __restrict__ small,
                            const float* __restrict__ disc_b, float* __restrict__ out) {
    int n = (blockIdx.x * blockDim.x + threadIdx.x) >> 5;
    int lane = threadIdx.x & 31;
    if (n >= N_NODES) return;
    float2 xo = *reinterpret_cast<const float2*>(x2 + (size_t)n * C2 + lane * 2);
    float2 xa = *reinterpret_cast<const float2*>(x2 + (size_t)(N_NODES + n) * C2 + lane * 2);
    float2 w1 = *reinterpret_cast<const float2*>(small + lane * 2);
    float2 w2 = *reinterpret_cast<const float2*>(small + 64 + lane * 2);
    float2 w3 = *reinterpret_cast<const float2*>(small + 128 + lane * 2);
    float p0 = warp_sum(xo.x * w1.x + xo.y * w1.y);
    float p1 = warp_sum(xa.x * w1.x + xa.y * w1.y);
    float p2 = warp_sum(xa.x * w2.x + xa.y * w2.y);
    float p3 = warp_sum(xo.x * w2.x + xo.y * w2.y);
    float p4 = warp_sum(xo.x * w3.x + xo.y * w3.y);
    float p5 = warp_sum(xa.x * w3.x + xa.y * w3.y);
    if (lane == 0) {
        float db = disc_b[0];
        float badv = small[192];
        out[OFF_RET + 2 * n] = p0 + db;
        out[OFF_RET + 2 * n + 1] = p1 + db;
        out[OFF_RETA + 2 * n] = p2 + db;
        out[OFF_RETA + 2 * n + 1] = p3 + db;
        out[OFF_LOGITS + n] = p4 + badv;
        out[OFF_LOGITS + N_NODES + n] = p5 + badv;
    }
    *reinterpret_cast<float2*>(out + OFF_X2 + (size_t)n * C2 + lane * 2) = xo;
}

// ---------------- entity decoder heads: log, log1 ----------------
__global__ void k_entityfinal(const float* __restrict__ fh, const float* __restrict__ fW2,
                              const float* __restrict__ fb2, const float* __restrict__ fW3,
                              const float* __restrict__ fb3, float* __restrict__ out) {
    int b = (blockIdx.x * blockDim.x + threadIdx.x) >> 5;
    int lane = threadIdx.x & 31;
    if (b >= BATCH) return;
    float a2x = 0.f, a2y = 0.f, a3x = 0.f, a3y = 0.f;
    for (int i = lane; i < DEC; i += 32) {
        float v = fh[(size_t)b * DEC + i];
        a2x += v * fW2[i * 2];
        a2y += v * fW2[i * 2 + 1];
        a3x += v * fW3[i * 2];
        a3y += v * fW3[i * 2 + 1];
    }
    a2x = warp_sum(a2x); a2y = warp_sum(a2y);
    a3x = warp_sum(a3x); a3y = warp_sum(a3y);
    if (lane == 0) {
        out[OFF_LOG + 2 * b] = a2x + fb2[0];
        out[OFF_LOG + 2 * b + 1] = a2y + fb2[1];
        out[OFF_LOG1 + 2 * b] = a3x + fb3[0];
        out[OFF_LOG1 + 2 * b + 1] = a3y + fb3[1];
    }
}

// ---------------- host launch ----------------
extern "C" void kernel_launch(void* const* d_in, const int* in_sizes, int n_in,
                              void* d_out, int out_size) {
    const float* x_o    = (const float*)d_in[0];
    const float* x_a    = (const float*)d_in[1];
    const int*   ei     = (const int*)d_in[2];
    const int*   idx    = (const int*)d_in[3];
    const float* W1     = (const float*)d_in[4];
    const float* a_src1 = (const float*)d_in[5];
    const float* a_dst1 = (const float*)d_in[6];
    const float* b1     = (const float*)d_in[7];
    const float* p1     = (const float*)d_in[8];
    const float* W2     = (const float*)d_in[9];
    const float* a_src2 = (const float*)d_in[10];
    const float* a_dst2 = (const float*)d_in[11];
    const float* b2     = (const float*)d_in[12];
    const float* p2     = (const float*)d_in[13];
    const float* mlp_W  = (const float*)d_in[14];
    const float* mlp_b  = (const float*)d_in[15];
    const float* disc_W = (const float*)d_in[16];
    const float* disc_b = (const float*)d_in[17];
    const float* adv_W  = (const float*)d_in[18];
    const float* adv_b  = (const float*)d_in[19];
    const float* f_W1   = (const float*)d_in[20];
    const float* f_b1   = (const float*)d_in[21];
    const float* f_W2   = (const float*)d_in[22];
    const float* f_b2   = (const float*)d_in[23];
    const float* f_W3   = (const float*)d_in[24];
    const float* f_b3   = (const float*)d_in[25];

    const int* e_src = ei;
    const int* e_dst = ei + N_EDGES;
    const int* idx0 = idx;
    const int* idx1 = idx + BATCH;

    __half *h1, *h2, *x1;
    float *x2, *as1, *ad1, *as2, *ad2, *sums, *small, *fh;
    int *cnt, *off, *cur, *csr, *bsum, *bpre;
    __nv_bfloat16 *whi, *wlo;
    cudaGetSymbolAddress((void**)&h1, g_h1);
    cudaGetSymbolAddress((void**)&x1, g_x1);
    cudaGetSymbolAddress((void**)&h2, g_h2);
    cudaGetSymbolAddress((void**)&x2, g_x2);
    cudaGetSymbolAddress((void**)&as1, g_as1);
    cudaGetSymbolAddress((void**)&ad1, g_ad1);
    cudaGetSymbolAddress((void**)&as2, g_as2);
    cudaGetSymbolAddress((void**)&ad2, g_ad2);
    cudaGetSymbolAddress((void**)&sums, g_sums);
    cudaGetSymbolAddress((void**)&small, g_small);
    cudaGetSymbolAddress((void**)&fh, g_fh);
    cudaGetSymbolAddress((void**)&cnt, g_cnt);
    cudaGetSymbolAddress((void**)&off, g_off);
    cudaGetSymbolAddress((void**)&cur, g_cur);
    cudaGetSymbolAddress((void**)&csr, g_csr);
    cudaGetSymbolAddress((void**)&bsum, g_bsum);
    cudaGetSymbolAddress((void**)&bpre, g_bpre);
    cudaGetSymbolAddress((void**)&whi, g_whi);
    cudaGetSymbolAddress((void**)&wlo, g_wlo);

    float* out = (float*)d_out;

    constexpr int SMEM_G1  = 8 * (64 * 40 + 32 * 136);    // 55296 (BM=64, BN=128)
    constexpr int SMEM_G2  = 8 * (128 * 40 + 32 * 72);    // 59392 (BM=128, BN=64)
    constexpr int SMEM_FUS = 8 * (128 * 40 + 32 * 136);   // 75776 (BM=128, BN=128)

    static cudaStream_t s1 = nullptr;
    static cudaEvent_t evFork = nullptr, evCsr = nullptr, evX2 = nullptr, evFus = nullptr;
    static bool init_done = false;
    if (!init_done) {
        cudaFuncSetAttribute(k_mma_gemm<64, 128, 2, 4, 1, 1, 1, 0>,
                             cudaFuncAttributeMaxDynamicSharedMemorySize, SMEM_G1);
        cudaFuncSetAttribute(k_mma_gemm<128, 64, 8, 1, 0, 2, 1, 1>,
                             cudaFuncAttributeMaxDynamicSharedMemorySize, SMEM_G2);
        cudaFuncSetAttribute(k_mma_gemm<128, 128, 2, 4, 2, 0, 0, 0>,
                             cudaFuncAttributeMaxDynamicSharedMemorySize, SMEM_FUS);
        cudaStreamCreateWithFlags(&s1, cudaStreamNonBlocking);
        cudaEventCreateWithFlags(&evFork, cudaEventDisableTiming);
        cudaEventCreateWithFlags(&evCsr, cudaEventDisableTiming);
        cudaEventCreateWithFlags(&evX2, cudaEventDisableTiming);
        cudaEventCreateWithFlags(&evFus, cudaEventDisableTiming);
        init_done = true;
    }

    constexpr int SCAN_BLOCKS = (N_NODES + 1023) / 1024;   // 49
    const int M2 = 2 * N_NODES;

    // launch 1 (main): weight pre-split
    k_splitW<<<(WSPLIT_TOTAL + 255) / 256, 256>>>(W1, W2, f_W1, whi, wlo);

    // fork side stream for CSR build
    cudaEventRecord(evFork, 0);
    cudaStreamWaitEvent(s1, evFork, 0);

    // launches 2-3 (s1): CSR chain, part 1
    k_zero<<<(N_NODES + 255) / 256, 256, 0, s1>>>(cnt, sums);
    k_hist<<<(N_EDGES + 255) / 256, 256, 0, s1>>>(e_dst, cnt);

    // launch 4 (main): layer 1 GEMM (BM=64, fp16 out) + fused logits  [ncu target]
    k_mma_gemm<64, 128, 2, 4, 1, 1, 1, 0><<<dim3(1, (M2 + 63) / 64), 256, SMEM_G1>>>(
        x_o, x_a, whi + WOFF_W1, wlo + WOFF_W1, nullptr, h1, M2, C1, D_IN, N_NODES,
        nullptr, nullptr, a_src1, a_dst1, as1, ad1);

    // launches 5-8 (s1): CSR chain, part 2
    k_scanA<<<SCAN_BLOCKS, 1024, 0, s1>>>(cnt, off, bsum);
    k_scanB<<<1, 64, 0, s1>>>(bsum, bpre, off, SCAN_BLOCKS);
    k_scanC<<<SCAN_BLOCKS, 1024, 0, s1>>>(off, cur, bpre);
    k_fill<<<(N_EDGES + 255) / 256, 256, 0, s1>>>(e_src, e_dst, cur, csr);
    cudaEventRecord(evCsr, s1);

    // join: agg1 needs CSR + GEMM1
    cudaStreamWaitEvent(0, evCsr, 0);
    k_agg1<<<N_NODES / 8, 256>>>(h1, as1, ad1, b1, p1, x1, off, csr);

    // layer 2 GEMM (fp16 in, fp16 out) + fused logits
    k_mma_gemm<128, 64, 8, 1, 0, 2, 1, 1><<<dim3(1, (M2 + 127) / 128), 256, SMEM_G2>>>(
        x1, nullptr, whi + WOFF_W2, wlo + WOFF_W2, nullptr, h2, M2, C2, C1, N_NODES,
        nullptr, nullptr, a_src2, a_dst2, as2, ad2);

    k_agg2<<<N_NODES / 8, 256>>>(h2, as2, ad2, b2, p2, x2, off, csr, sums);

    // ---- fork after x2: fusion decoder on s1, readout heads on main ----
    cudaEventRecord(evX2, 0);
    cudaStreamWaitEvent(s1, evX2, 0);

    // s1: fusion decoder + entity heads (OFF_LOG / OFF_LOG1 regions)
    k_mma_gemm<128, 128, 2, 4, 2, 0, 0, 0><<<dim3(DEC / 128, BATCH / 128), 256, SMEM_FUS, s1>>>(
        x2, nullptr, whi + WOFF_FW1, wlo + WOFF_FW1, f_b1, fh, BATCH, DEC, 2 * C2, 0,
        idx0, idx1, nullptr, nullptr, nullptr, nullptr);
    k_entityfinal<<<(BATCH + 7) / 8, 256, 0, s1>>>(fh, f_W2, f_b2, f_W3, f_b3, out);
    cudaEventRecord(evFus, s1);

    // main: readout + per-node heads (RET/RETA/X2/LOGITS regions)
    k_small<<<1, 64>>>(sums, mlp_W, mlp_b, disc_W, adv_W, adv_b, small);
    k_nodefinal<<<(N_NODES + 7) / 8, 256>>>(x2, small, disc_b, out);

    // join before returning to harness
    cudaStreamWaitEvent(0, evFus, 0);
}